// round 3
// baseline (speedup 1.0000x reference)
#include <cuda_runtime.h>
#include <math.h>

#define BB 2
#define LL 2048
#define DD 256
#define HH 8
#define HD 32
#define BH (BB*HH)
#define QT 16            // q-rows per block in fused kernel
#define PITCH 2052       // Srow row pitch (floats): breaks bank alignment of rows
#define VPITCH 36        // Vs row pitch

// ---------------- scratch (device globals; no allocation allowed) ----------
__device__ float g_Q[(size_t)BB*HH*LL*HD];     // 4 MB  [b,h,l,d]
__device__ float g_K[(size_t)BB*HH*LL*HD];     // 4 MB
__device__ float g_V[(size_t)BB*HH*LL*HD];     // 4 MB
__device__ float g_O[(size_t)BB*HH*LL*HD];     // 4 MB  attn@V heads
__device__ float g_E[HH*LL];                   // prior exp table per head
__device__ float g_rs[HH*LL];                  // prior row sums
__device__ float g_dpart[(size_t)BB*HH*128*LL];// 16.8MB discrepancy partials

// ---------------- helpers --------------------------------------------------
__device__ __forceinline__ float warpMax(float v){
    #pragma unroll
    for (int o=16;o;o>>=1) v = fmaxf(v, __shfl_xor_sync(0xffffffffu, v, o));
    return v;
}
__device__ __forceinline__ float warpSum(float v){
    #pragma unroll
    for (int o=16;o;o>>=1) v += __shfl_xor_sync(0xffffffffu, v, o);
    return v;
}

// ---------------- kernel 1: QKV projection --------------------------------
__global__ __launch_bounds__(256) void qkv_kernel(
    const float* __restrict__ x,
    const float* __restrict__ Wq, const float* __restrict__ bq,
    const float* __restrict__ Wk, const float* __restrict__ bk,
    const float* __restrict__ Wv, const float* __restrict__ bv)
{
    __shared__ float Xs[64][33];
    __shared__ float Ws[64][33];
    const float* Wm; const float* bm; float* outp;
    if (blockIdx.z == 0)      { Wm=Wq; bm=bq; outp=g_Q; }
    else if (blockIdx.z == 1) { Wm=Wk; bm=bk; outp=g_K; }
    else                      { Wm=Wv; bm=bv; outp=g_V; }

    const int m0 = blockIdx.y*64, n0 = blockIdx.x*64;
    const int tid = threadIdx.x, tx = tid & 15, ty = tid >> 4;
    float acc[4][4] = {};

    for (int k0 = 0; k0 < DD; k0 += 32) {
        for (int idx = tid; idx < 2048; idx += 256) {
            int r = idx >> 5, c = idx & 31;
            Xs[r][c] = x[(size_t)(m0+r)*DD + k0 + c];
            Ws[r][c] = Wm[(size_t)(n0+r)*DD + k0 + c];
        }
        __syncthreads();
        #pragma unroll
        for (int kk = 0; kk < 32; kk++) {
            float a[4], w[4];
            #pragma unroll
            for (int i=0;i<4;i++) a[i] = Xs[ty*4+i][kk];
            #pragma unroll
            for (int j=0;j<4;j++) w[j] = Ws[tx*4+j][kk];
            #pragma unroll
            for (int i=0;i<4;i++)
                #pragma unroll
                for (int j=0;j<4;j++) acc[i][j] += a[i]*w[j];
        }
        __syncthreads();
    }
    #pragma unroll
    for (int i=0;i<4;i++){
        int m = m0 + ty*4 + i;
        int b = m >> 11, l = m & (LL-1);
        #pragma unroll
        for (int j=0;j<4;j++){
            int n = n0 + tx*4 + j;
            int h = n >> 5, d = n & 31;
            outp[(((size_t)(b*HH + h))*LL + l)*HD + d] = acc[i][j] + bm[n];
        }
    }
}

// ---------------- kernel 2a: prior exp table -------------------------------
__global__ void prior_e_kernel(const float* __restrict__ u)
{
    int h = blockIdx.x;
    float uv = u[h];
    float c = 0.5f / (uv*uv + 1e-6f);
    for (int d = threadIdx.x; d < LL; d += blockDim.x) {
        float fd = (float)d;
        g_E[h*LL + d] = expf(-(fd*fd) * c);
    }
}

// ---------------- kernel 2b: prior row sums --------------------------------
__global__ __launch_bounds__(256) void prior_rs_kernel()
{
    __shared__ float Es[LL];
    int h = blockIdx.y;
    for (int i = threadIdx.x; i < LL; i += 256) Es[i] = g_E[h*LL + i];
    __syncthreads();
    int q = blockIdx.x*256 + threadIdx.x;
    float s = 0.f;
    for (int k = 0; k < LL; k++) s += Es[abs(q - k)];
    g_rs[h*LL + q] = s;
}

// ---------------- kernel 3: FULLY FUSED scores+softmax+disc+AV -------------
// Block: (bh, 16 q-rows), 512 threads. Never writes attn to DRAM.
// Dyn smem (floats):
//   Srow[16*PITCH] | Ks[512*33] (reused as Vs[256*36]) | Es[2048] |
//   irs[16] | Opart[4*16*32]
#define SMF_SROW 0
#define SMF_KS   (QT*PITCH)                  // 32832
#define SMF_ES   (SMF_KS + 512*33)           // +16896
#define SMF_IRS  (SMF_ES + LL)               // +2048
#define SMF_OP   (SMF_IRS + 16)              // +16
#define SMF_QS   (SMF_OP + 4*16*32)          // +2048
#define SMF_TOT  (SMF_QS + QT*33)            // +528
#define SMF_BYTES (SMF_TOT*4)

__global__ __launch_bounds__(512,1) void attn_fused_kernel()
{
    extern __shared__ float sm[];
    float* Srow = sm + SMF_SROW;
    float* Ks   = sm + SMF_KS;
    float* Vs   = sm + SMF_KS;     // reused after phase 1
    float* Es   = sm + SMF_ES;
    float* irs  = sm + SMF_IRS;
    float* Op   = sm + SMF_OP;
    float* Qs   = sm + SMF_QS;

    const int tid = threadIdx.x;
    const int qt  = blockIdx.x;
    const int bh  = blockIdx.y;
    const int b   = bh >> 3, h = bh & 7;
    const int q0  = qt * QT;
    const float SCALE = 0.17677669529663687f;  // 1/sqrt(32)

    const float* Qp = g_Q + (size_t)bh*LL*HD;
    const float* Kp = g_K + (size_t)bh*LL*HD;
    const float* Vp = g_V + (size_t)bh*LL*HD;

    // ---- phase 0: Q tile (scaled), E table, inv row sums ------------------
    if (tid < QT*HD) {
        int r = tid >> 5, d = tid & 31;
        Qs[r*33 + d] = Qp[(size_t)(q0+r)*HD + d] * SCALE;
    }
    for (int idx = tid; idx < LL; idx += 512) Es[idx] = g_E[h*LL + idx];
    if (tid < QT) irs[tid] = 1.0f / (g_rs[h*LL + q0 + tid] + 1e-6f);

    // ---- phase 1: scores. Two 256-k chunks in flight (one per half-block) --
    const float4* Kp4 = (const float4*)Kp;
    const int half = tid >> 8;              // 0/1: which 256-k chunk
    const int t256 = tid & 255;
    const int tx = t256 & 63, ty = t256 >> 6;
    float4 pre[8];
    #pragma unroll
    for (int t = 0; t < 8; t++) pre[t] = Kp4[tid + t*512];

    for (int kc = 0; kc < 4; kc++) {        // 512 k per iteration
        #pragma unroll
        for (int t = 0; t < 8; t++) {
            int f4 = tid + t*512;
            int r = f4 >> 3, c4 = f4 & 7;
            float* p = &Ks[r*33 + c4*4];
            p[0]=pre[t].x; p[1]=pre[t].y; p[2]=pre[t].z; p[3]=pre[t].w;
        }
        __syncthreads();
        if (kc < 3) {
            #pragma unroll
            for (int t = 0; t < 8; t++)
                pre[t] = Kp4[(kc+1)*4096 + tid + t*512];
        }
        float acc[4][4] = {};
        #pragma unroll
        for (int kk = 0; kk < 32; kk++) {
            float a[4], bv[4];
            #pragma unroll
            for (int i=0;i<4;i++) a[i]  = Qs[(ty + 4*i)*33 + kk];
            #pragma unroll
            for (int j=0;j<4;j++) bv[j] = Ks[(half*256 + tx + 64*j)*33 + kk];
            #pragma unroll
            for (int i=0;i<4;i++)
                #pragma unroll
                for (int j=0;j<4;j++) acc[i][j] += a[i]*bv[j];
        }
        #pragma unroll
        for (int i=0;i<4;i++)
            #pragma unroll
            for (int j=0;j<4;j++)
                Srow[(ty+4*i)*PITCH + kc*512 + half*256 + tx + 64*j] = acc[i][j];
        __syncthreads();
    }

    // ---- phase 2: softmax, one warp per row, normalized in place ----------
    {
        const int w = tid >> 5, lane = tid & 31;
        float* R = Srow + w*PITCH;
        float m = -3.4e38f;
        #pragma unroll 4
        for (int k = lane; k < LL; k += 32) m = fmaxf(m, R[k]);
        m = warpMax(m);
        float s = 0.f;
        #pragma unroll 4
        for (int k = lane; k < LL; k += 32) {
            float e = __expf(R[k] - m);
            R[k] = e;
            s += e;
        }
        s = warpSum(s);
        float iv = 1.0f / s;
        #pragma unroll 4
        for (int k = lane; k < LL; k += 32) R[k] *= iv;
    }
    __syncthreads();

    // ---- phase 3: discrepancy partials ------------------------------------
    {
        size_t pbase = (((size_t)(b*HH + h))*128 + qt) * LL;
        #pragma unroll
        for (int t = 0; t < 4; t++) {
            int k = tid + t*512;
            float acc = 0.f;
            #pragma unroll
            for (int q = 0; q < QT; q++) {
                float a = Srow[q*PITCH + k];
                float p = Es[abs(q0 + q - k)] * irs[q];
                acc += fabsf(a - p);
            }
            g_dpart[pbase + k] = acc;
        }
    }

    // ---- phase 4: O = attn @ V --------------------------------------------
    // 16 warps: qg = w>>2 (4 q rows), ks = w&3 (64-k slice of each 256 chunk)
    {
        const int w = tid >> 5, lane = tid & 31;
        const int qg = w >> 2, ks = w & 3;
        const int q  = qg*4 + (lane >> 3);
        const int d4 = lane & 7;
        const float4* Vp4 = (const float4*)Vp;
        float4 acc4 = make_float4(0.f,0.f,0.f,0.f);

        for (int ch = 0; ch < 8; ch++) {     // 256 k per chunk
            __syncthreads();                 // prev chunk compute done
            #pragma unroll
            for (int t = 0; t < 4; t++) {
                int f4 = tid + t*512;        // 2048 f4 per chunk
                int r = f4 >> 3, c4 = f4 & 7;
                float4 v = Vp4[ch*2048 + f4];
                float* p = &Vs[r*VPITCH + c4*4];
                p[0]=v.x; p[1]=v.y; p[2]=v.z; p[3]=v.w;
            }
            __syncthreads();
            const float* Sr = Srow + q*PITCH + ch*256 + ks*64;
            const float* Vr = Vs + (ks*64)*VPITCH + d4*4;
            #pragma unroll 8
            for (int kk = 0; kk < 64; kk++) {
                float s = Sr[kk];
                float4 v = *(const float4*)(Vr + kk*VPITCH);
                acc4.x += s*v.x; acc4.y += s*v.y;
                acc4.z += s*v.z; acc4.w += s*v.w;
            }
        }
        float* po = &Op[(ks*16 + q)*32 + d4*4];
        po[0]=acc4.x; po[1]=acc4.y; po[2]=acc4.z; po[3]=acc4.w;
    }
    __syncthreads();

    // reduce 4 k-slices and write O
    {
        int q = tid >> 5, d = tid & 31;
        float s = Op[q*32 + d] + Op[512 + q*32 + d]
                + Op[1024 + q*32 + d] + Op[1536 + q*32 + d];
        g_O[((size_t)bh*LL + q0 + q)*HD + d] = s;
    }
}

// ---------------- kernel 4: discrepancy reduce -----------------------------
__global__ void disc_reduce_kernel(float* __restrict__ dout)
{
    int idx = blockIdx.x*256 + threadIdx.x;   // < B*L
    int b = idx >> 11, k = idx & (LL-1);
    float s = 0.f;
    const float* base = g_dpart + (size_t)b*HH*128*LL + k;
    for (int p = 0; p < HH*128; p++) s += base[(size_t)p*LL];
    dout[idx] = s * (1.0f/(HH*(float)LL));
}

// ---------------- kernel 5: out projection ---------------------------------
__global__ __launch_bounds__(256) void outproj_kernel(
    const float* __restrict__ Wo, const float* __restrict__ bo,
    float* __restrict__ out)
{
    __shared__ float Xs[64][33];
    __shared__ float Ws[64][33];
    const int m0 = blockIdx.y*64, n0 = blockIdx.x*64;
    const int tid = threadIdx.x, tx = tid & 15, ty = tid >> 4;
    float acc[4][4] = {};

    for (int k0 = 0; k0 < DD; k0 += 32) {
        int h = k0 >> 5;
        for (int idx = tid; idx < 2048; idx += 256) {
            int r = idx >> 5, c = idx & 31;
            int m = m0 + r;
            int b = m >> 11, l = m & (LL-1);
            Xs[r][c] = g_O[(((size_t)(b*HH + h))*LL + l)*HD + c];
            Ws[r][c] = Wo[(size_t)(n0+r)*DD + k0 + c];
        }
        __syncthreads();
        #pragma unroll
        for (int kk = 0; kk < 32; kk++) {
            float a[4], w[4];
            #pragma unroll
            for (int i=0;i<4;i++) a[i] = Xs[ty*4+i][kk];
            #pragma unroll
            for (int j=0;j<4;j++) w[j] = Ws[tx*4+j][kk];
            #pragma unroll
            for (int i=0;i<4;i++)
                #pragma unroll
                for (int j=0;j<4;j++) acc[i][j] += a[i]*w[j];
        }
        __syncthreads();
    }
    #pragma unroll
    for (int i=0;i<4;i++){
        int m = m0 + ty*4 + i;
        #pragma unroll
        for (int j=0;j<4;j++){
            int n = n0 + tx*4 + j;
            out[(size_t)m*DD + n] = acc[i][j] + bo[n];
        }
    }
}

// ---------------- launch ---------------------------------------------------
extern "C" void kernel_launch(void* const* d_in, const int* in_sizes, int n_in,
                              void* d_out, int out_size)
{
    const float* x  = (const float*)d_in[0];
    const float* Wq = (const float*)d_in[1];
    const float* bq = (const float*)d_in[2];
    const float* Wk = (const float*)d_in[3];
    const float* bk = (const float*)d_in[4];
    const float* Wv = (const float*)d_in[5];
    const float* bv = (const float*)d_in[6];
    const float* u  = (const float*)d_in[7];
    const float* Wo = (const float*)d_in[8];
    const float* bo = (const float*)d_in[9];
    float* out = (float*)d_out;

    cudaFuncSetAttribute(attn_fused_kernel,
                         cudaFuncAttributeMaxDynamicSharedMemorySize, SMF_BYTES);

    qkv_kernel<<<dim3(DD/64, (BB*LL)/64, 3), 256>>>(x, Wq, bq, Wk, bk, Wv, bv);
    prior_e_kernel<<<HH, 256>>>(u);
    prior_rs_kernel<<<dim3(LL/256, HH), 256>>>();
    attn_fused_kernel<<<dim3(LL/QT, BH), 512, SMF_BYTES>>>();
    disc_reduce_kernel<<<(BB*LL)/256, 256>>>(out + (size_t)BB*LL*DD);
    outproj_kernel<<<dim3(DD/64, (BB*LL)/64), 256>>>(Wo, bo, out);
}

// round 4
// speedup vs baseline: 1.2408x; 1.2408x over previous
#include <cuda_runtime.h>
#include <math.h>

#define BB 2
#define LL 2048
#define DD 256
#define HH 8
#define HD 32
#define BH (BB*HH)
#define QT 16            // q-rows per block in fused kernel
#define SPITCH 2056      // Srow pitch: 2056 % 32 == 8 -> phase-4 conflict-free
#define QPITCH 34        // Qs pitch (even -> 8B-aligned float2 loads)
#define VPITCH 36        // Vs pitch (16B-aligned float4)

// ---------------- scratch (device globals; no allocation allowed) ----------
__device__ float g_Q[(size_t)BB*HH*LL*HD];     // 4 MB  [b,h,l,d]
__device__ float g_K[(size_t)BB*HH*LL*HD];     // 4 MB
__device__ float g_V[(size_t)BB*HH*LL*HD];     // 4 MB
__device__ float g_O[(size_t)BB*HH*LL*HD];     // 4 MB  attn@V heads
__device__ float g_E[HH*LL];                   // prior exp table per head
__device__ float g_rs[HH*LL];                  // prior row sums
__device__ float g_dpart[(size_t)BB*HH*128*LL];// 16.8MB discrepancy partials
__device__ float g_dpart2[16*BB*LL];           // stage-2 partials

// ---------------- helpers --------------------------------------------------
__device__ __forceinline__ float warpMax(float v){
    #pragma unroll
    for (int o=16;o;o>>=1) v = fmaxf(v, __shfl_xor_sync(0xffffffffu, v, o));
    return v;
}
__device__ __forceinline__ float warpSum(float v){
    #pragma unroll
    for (int o=16;o;o>>=1) v += __shfl_xor_sync(0xffffffffu, v, o);
    return v;
}

// ---------------- kernel 1: QKV projection --------------------------------
__global__ __launch_bounds__(256) void qkv_kernel(
    const float* __restrict__ x,
    const float* __restrict__ Wq, const float* __restrict__ bq,
    const float* __restrict__ Wk, const float* __restrict__ bk,
    const float* __restrict__ Wv, const float* __restrict__ bv)
{
    __shared__ float Xs[64][33];
    __shared__ float Ws[64][33];
    const float* Wm; const float* bm; float* outp;
    if (blockIdx.z == 0)      { Wm=Wq; bm=bq; outp=g_Q; }
    else if (blockIdx.z == 1) { Wm=Wk; bm=bk; outp=g_K; }
    else                      { Wm=Wv; bm=bv; outp=g_V; }

    const int m0 = blockIdx.y*64, n0 = blockIdx.x*64;
    const int tid = threadIdx.x, tx = tid & 15, ty = tid >> 4;
    float acc[4][4] = {};

    for (int k0 = 0; k0 < DD; k0 += 32) {
        for (int idx = tid; idx < 2048; idx += 256) {
            int r = idx >> 5, c = idx & 31;
            Xs[r][c] = x[(size_t)(m0+r)*DD + k0 + c];
            Ws[r][c] = Wm[(size_t)(n0+r)*DD + k0 + c];
        }
        __syncthreads();
        #pragma unroll
        for (int kk = 0; kk < 32; kk++) {
            float a[4], w[4];
            #pragma unroll
            for (int i=0;i<4;i++) a[i] = Xs[ty*4+i][kk];
            #pragma unroll
            for (int j=0;j<4;j++) w[j] = Ws[tx*4+j][kk];
            #pragma unroll
            for (int i=0;i<4;i++)
                #pragma unroll
                for (int j=0;j<4;j++) acc[i][j] += a[i]*w[j];
        }
        __syncthreads();
    }
    #pragma unroll
    for (int i=0;i<4;i++){
        int m = m0 + ty*4 + i;
        int b = m >> 11, l = m & (LL-1);
        #pragma unroll
        for (int j=0;j<4;j++){
            int n = n0 + tx*4 + j;
            int h = n >> 5, d = n & 31;
            outp[(((size_t)(b*HH + h))*LL + l)*HD + d] = acc[i][j] + bm[n];
        }
    }
}

// ---------------- kernel 2a: prior exp table -------------------------------
__global__ void prior_e_kernel(const float* __restrict__ u)
{
    int h = blockIdx.x;
    float uv = u[h];
    float c = 0.5f / (uv*uv + 1e-6f);
    for (int d = threadIdx.x; d < LL; d += blockDim.x) {
        float fd = (float)d;
        g_E[h*LL + d] = expf(-(fd*fd) * c);
    }
}

// ---------------- kernel 2b: prior row sums --------------------------------
__global__ __launch_bounds__(256) void prior_rs_kernel()
{
    __shared__ float Es[LL];
    int h = blockIdx.y;
    for (int i = threadIdx.x; i < LL; i += 256) Es[i] = g_E[h*LL + i];
    __syncthreads();
    int q = blockIdx.x*256 + threadIdx.x;
    float s = 0.f;
    for (int k = 0; k < LL; k++) s += Es[abs(q - k)];
    g_rs[h*LL + q] = s;
}

// ---------------- kernel 3: FULLY FUSED scores+softmax+disc+AV -------------
// Dyn smem (floats):
//   Srow[16*SPITCH] | Ks[512*33] (reused as Vs[256*36]) | Es[2048] |
//   Qs[16*34] | inv[16] | irs[16]
#define SMF_SROW 0
#define SMF_KS   (QT*SPITCH)                 // 32896
#define SMF_ES   (SMF_KS + 512*33)           // +16896
#define SMF_QS   (SMF_ES + LL)               // +2048
#define SMF_INV  (SMF_QS + QT*QPITCH)        // +544
#define SMF_IRS  (SMF_INV + QT)              // +16
#define SMF_TOT  (SMF_IRS + QT)
#define SMF_BYTES (SMF_TOT*4)

__global__ __launch_bounds__(512,1) void attn_fused_kernel()
{
    extern __shared__ float sm[];
    float* Srow = sm + SMF_SROW;
    float* Ks   = sm + SMF_KS;
    float* Vs   = sm + SMF_KS;     // reused in phase 4
    float* Es   = sm + SMF_ES;
    float* Qs   = sm + SMF_QS;
    float* inv  = sm + SMF_INV;
    float* irs  = sm + SMF_IRS;

    const int tid = threadIdx.x;
    const int qt  = blockIdx.x;
    const int bh  = blockIdx.y;
    const int b   = bh >> 3, h = bh & 7;
    const int q0  = qt * QT;
    const float SCALE = 0.17677669529663687f;  // 1/sqrt(32)

    const float* Qp = g_Q + (size_t)bh*LL*HD;
    const float* Kp = g_K + (size_t)bh*LL*HD;
    const float* Vp = g_V + (size_t)bh*LL*HD;

    // ---- phase 0: Q tile (scaled), E table, inv prior row sums ------------
    if (tid < QT*HD) {
        int r = tid >> 5, d = tid & 31;
        Qs[r*QPITCH + d] = Qp[(size_t)(q0+r)*HD + d] * SCALE;
    }
    for (int idx = tid; idx < LL; idx += 512) Es[idx] = g_E[h*LL + idx];
    if (tid < QT) irs[tid] = 1.0f / (g_rs[h*LL + q0 + tid] + 1e-6f);

    // ---- phase 1: scores. 512 threads on one 512-k chunk, 4q x 4k tiles ---
    const float4* Kp4 = (const float4*)Kp;
    const int tx = tid & 127, ty = tid >> 7;    // ty 0..3 -> q rows ty+4i
    float4 pre[8];
    #pragma unroll
    for (int t = 0; t < 8; t++) pre[t] = Kp4[tid + t*512];

    for (int kc = 0; kc < 4; kc++) {            // 512 k per iteration
        #pragma unroll
        for (int t = 0; t < 8; t++) {
            int f4 = tid + t*512;
            int r = f4 >> 3, c4 = f4 & 7;
            float* p = &Ks[r*33 + c4*4];
            p[0]=pre[t].x; p[1]=pre[t].y; p[2]=pre[t].z; p[3]=pre[t].w;
        }
        __syncthreads();
        if (kc < 3) {
            #pragma unroll
            for (int t = 0; t < 8; t++)
                pre[t] = Kp4[(kc+1)*4096 + tid + t*512];
        }
        float acc[4][4] = {};
        #pragma unroll
        for (int kk = 0; kk < 32; kk += 2) {
            float2 a2[4];
            float bvA[4], bvB[4];
            #pragma unroll
            for (int i=0;i<4;i++)
                a2[i] = *(const float2*)&Qs[(ty + 4*i)*QPITCH + kk];
            #pragma unroll
            for (int j=0;j<4;j++) {
                bvA[j] = Ks[(tx + 128*j)*33 + kk];
                bvB[j] = Ks[(tx + 128*j)*33 + kk + 1];
            }
            #pragma unroll
            for (int i=0;i<4;i++)
                #pragma unroll
                for (int j=0;j<4;j++)
                    acc[i][j] += a2[i].x*bvA[j] + a2[i].y*bvB[j];
        }
        #pragma unroll
        for (int i=0;i<4;i++)
            #pragma unroll
            for (int j=0;j<4;j++)
                Srow[(ty+4*i)*SPITCH + kc*512 + tx + 128*j] = acc[i][j];
        __syncthreads();
    }

    // ---- phase 2: softmax (max + exp/sum; leaves unnormalized e) ----------
    {
        const int w = tid >> 5, lane = tid & 31;
        float* R = Srow + w*SPITCH;
        float m = -3.4e38f;
        #pragma unroll 8
        for (int k = lane; k < LL; k += 32) m = fmaxf(m, R[k]);
        m = warpMax(m);
        float s = 0.f;
        #pragma unroll 8
        for (int k = lane; k < LL; k += 32) {
            float e = __expf(R[k] - m);
            R[k] = e;
            s += e;
        }
        s = warpSum(s);
        if (lane == 0) inv[w] = 1.0f / s;
    }
    __syncthreads();

    // ---- phase 3: discrepancy partials (reads raw e, normalizes on fly) ---
    {
        size_t pbase = (((size_t)(b*HH + h))*128 + qt) * LL;
        #pragma unroll
        for (int t = 0; t < 4; t++) {
            int k = tid + t*512;
            float acc = 0.f;
            #pragma unroll
            for (int q = 0; q < QT; q++) {
                float a = Srow[q*SPITCH + k] * inv[q];
                float p = Es[abs(q0 + q - k)] * irs[q];
                acc += fabsf(a - p);
            }
            g_dpart[pbase + k] = acc;
        }
    }

    // ---- phase 4: O = attn @ V --------------------------------------------
    // warp = (qg,dg) 4q x 8d patch; lane = (qi=lane&3, ki=lane>>2)
    {
        const int w = tid >> 5, lane = tid & 31;
        const int qg = w >> 2, dg = w & 3;
        const int qi = lane & 3, ki = lane >> 2;
        const int q  = qg*4 + qi;
        const float iv = inv[q];
        const float4* Vp4 = (const float4*)Vp;
        float acc[8] = {};

        for (int ch = 0; ch < 8; ch++) {        // 256 k per chunk
            __syncthreads();                    // prev compute / disc done
            #pragma unroll
            for (int t = 0; t < 4; t++) {
                int f4 = tid + t*512;           // 2048 f4 = 256x32
                int r = f4 >> 3, c4 = f4 & 7;
                *(float4*)&Vs[r*VPITCH + c4*4] = Vp4[ch*2048 + f4];
            }
            __syncthreads();
            const float* Sr = Srow + q*SPITCH + ch*256;
            #pragma unroll 4
            for (int kb = 0; kb < 32; kb++) {
                int kl = kb*8 + ki;
                float a = Sr[kl] * iv;
                float4 v0 = *(const float4*)&Vs[kl*VPITCH + dg*8];
                float4 v1 = *(const float4*)&Vs[kl*VPITCH + dg*8 + 4];
                acc[0] += a*v0.x; acc[1] += a*v0.y;
                acc[2] += a*v0.z; acc[3] += a*v0.w;
                acc[4] += a*v1.x; acc[5] += a*v1.y;
                acc[6] += a*v1.z; acc[7] += a*v1.w;
            }
        }
        // reduce across the 8 ki-lanes (strides 4,8,16)
        #pragma unroll
        for (int off = 4; off < 32; off <<= 1)
            #pragma unroll
            for (int r = 0; r < 8; r++)
                acc[r] += __shfl_down_sync(0xffffffffu, acc[r], off);
        if (lane < 4) {
            float4* dst = (float4*)&g_O[((size_t)bh*LL + q0 + q)*HD + dg*8];
            dst[0] = make_float4(acc[0],acc[1],acc[2],acc[3]);
            dst[1] = make_float4(acc[4],acc[5],acc[6],acc[7]);
        }
    }
}

// ---------------- kernel 4: discrepancy reduce (2-stage) -------------------
__global__ void disc_reduce1_kernel()
{
    int k = blockIdx.x*256 + threadIdx.x;    // < B*L
    int seg = blockIdx.y;                    // 16 segments of 64 partials
    int b = k >> 11, kk = k & (LL-1);
    const float* base = g_dpart + (size_t)b*HH*128*LL + kk;
    float s = 0.f;
    #pragma unroll 8
    for (int p = seg*64; p < seg*64 + 64; p++) s += base[(size_t)p*LL];
    g_dpart2[seg*BB*LL + k] = s;
}

__global__ void disc_reduce2_kernel(float* __restrict__ dout)
{
    int idx = blockIdx.x*256 + threadIdx.x;  // < B*L
    float s = 0.f;
    #pragma unroll
    for (int seg = 0; seg < 16; seg++) s += g_dpart2[seg*BB*LL + idx];
    dout[idx] = s * (1.0f/(HH*(float)LL));
}

// ---------------- kernel 5: out projection ---------------------------------
__global__ __launch_bounds__(256) void outproj_kernel(
    const float* __restrict__ Wo, const float* __restrict__ bo,
    float* __restrict__ out)
{
    __shared__ float Xs[64][33];
    __shared__ float Ws[64][33];
    const int m0 = blockIdx.y*64, n0 = blockIdx.x*64;
    const int tid = threadIdx.x, tx = tid & 15, ty = tid >> 4;
    float acc[4][4] = {};

    for (int k0 = 0; k0 < DD; k0 += 32) {
        int h = k0 >> 5;
        for (int idx = tid; idx < 2048; idx += 256) {
            int r = idx >> 5, c = idx & 31;
            int m = m0 + r;
            int b = m >> 11, l = m & (LL-1);
            Xs[r][c] = g_O[(((size_t)(b*HH + h))*LL + l)*HD + c];
            Ws[r][c] = Wo[(size_t)(n0+r)*DD + k0 + c];
        }
        __syncthreads();
        #pragma unroll
        for (int kk = 0; kk < 32; kk++) {
            float a[4], w[4];
            #pragma unroll
            for (int i=0;i<4;i++) a[i] = Xs[ty*4+i][kk];
            #pragma unroll
            for (int j=0;j<4;j++) w[j] = Ws[tx*4+j][kk];
            #pragma unroll
            for (int i=0;i<4;i++)
                #pragma unroll
                for (int j=0;j<4;j++) acc[i][j] += a[i]*w[j];
        }
        __syncthreads();
    }
    #pragma unroll
    for (int i=0;i<4;i++){
        int m = m0 + ty*4 + i;
        #pragma unroll
        for (int j=0;j<4;j++){
            int n = n0 + tx*4 + j;
            out[(size_t)m*DD + n] = acc[i][j] + bo[n];
        }
    }
}

// ---------------- launch ---------------------------------------------------
extern "C" void kernel_launch(void* const* d_in, const int* in_sizes, int n_in,
                              void* d_out, int out_size)
{
    const float* x  = (const float*)d_in[0];
    const float* Wq = (const float*)d_in[1];
    const float* bq = (const float*)d_in[2];
    const float* Wk = (const float*)d_in[3];
    const float* bk = (const float*)d_in[4];
    const float* Wv = (const float*)d_in[5];
    const float* bv = (const float*)d_in[6];
    const float* u  = (const float*)d_in[7];
    const float* Wo = (const float*)d_in[8];
    const float* bo = (const float*)d_in[9];
    float* out = (float*)d_out;

    cudaFuncSetAttribute(attn_fused_kernel,
                         cudaFuncAttributeMaxDynamicSharedMemorySize, SMF_BYTES);

    qkv_kernel<<<dim3(DD/64, (BB*LL)/64, 3), 256>>>(x, Wq, bq, Wk, bk, Wv, bv);
    prior_e_kernel<<<HH, 256>>>(u);
    prior_rs_kernel<<<dim3(LL/256, HH), 256>>>();
    attn_fused_kernel<<<dim3(LL/QT, BH), 512, SMF_BYTES>>>();
    disc_reduce1_kernel<<<dim3((BB*LL)/256, 16), 256>>>();
    disc_reduce2_kernel<<<(BB*LL)/256, 256>>>(out + (size_t)BB*LL*DD);
    outproj_kernel<<<dim3(DD/64, (BB*LL)/64), 256>>>(Wo, bo, out);
}

// round 7
// speedup vs baseline: 1.6162x; 1.3025x over previous
#include <cuda_runtime.h>
#include <cuda_bf16.h>
#include <cuda_fp16.h>
#include <math.h>
#include <stdint.h>

#define BB 2
#define LL 2048
#define DD 256
#define HH 8
#define HD 32
#define BH (BB*HH)
#define QT 16
#define SPITCH 2060      // Srow pitch in floats; 2060*? -> 12*r mod32 distinct banks
#define PHPITCH (SPITCH*2)   // same rows viewed as halves (uint32 pitch == SPITCH)

// ---------------- scratch (device globals; no allocation allowed) ----------
__device__ float         g_V  [(size_t)BH*LL*HD];    // 4 MB fp32 V [bh][l][d]
__device__ float         g_O  [(size_t)BH*LL*HD];    // 4 MB attn@V heads
__device__ __nv_bfloat16 g_Q16[(size_t)BH*LL*64];    // rows [Qhi d0..31 | Qlo d0..31] (scaled)
__device__ __nv_bfloat16 g_K16[(size_t)BH*LL*64];    // rows [Khi | Klo]
__device__ __half        g_VT16[(size_t)BH*64*LL];   // [bh][hi d / 32+lo d][l]
__device__ float         g_E  [HH*LL];               // prior exp table
__device__ float         g_rs [HH*LL];               // prior row sums
__device__ float         g_dpart[(size_t)BB*HH*128*LL]; // disc partials
__device__ float         g_dpart2[16*BB*LL];            // stage-2 partials

// ---------------- helpers ----------------------------------------------------
__device__ __forceinline__ float warpMax(float v){
    #pragma unroll
    for (int o=16;o;o>>=1) v = fmaxf(v, __shfl_xor_sync(0xffffffffu, v, o));
    return v;
}
__device__ __forceinline__ float warpSum(float v){
    #pragma unroll
    for (int o=16;o;o>>=1) v += __shfl_xor_sync(0xffffffffu, v, o);
    return v;
}
__device__ __forceinline__ void mma_bf16(float* c, const uint32_t* a,
                                         uint32_t b0, uint32_t b1){
    asm volatile(
        "mma.sync.aligned.m16n8k16.row.col.f32.bf16.bf16.f32 "
        "{%0,%1,%2,%3}, {%4,%5,%6,%7}, {%8,%9}, {%0,%1,%2,%3};"
        : "+f"(c[0]), "+f"(c[1]), "+f"(c[2]), "+f"(c[3])
        : "r"(a[0]), "r"(a[1]), "r"(a[2]), "r"(a[3]), "r"(b0), "r"(b1));
}
__device__ __forceinline__ void mma_f16(float* c, const uint32_t* a,
                                        uint32_t b0, uint32_t b1){
    asm volatile(
        "mma.sync.aligned.m16n8k16.row.col.f32.f16.f16.f32 "
        "{%0,%1,%2,%3}, {%4,%5,%6,%7}, {%8,%9}, {%0,%1,%2,%3};"
        : "+f"(c[0]), "+f"(c[1]), "+f"(c[2]), "+f"(c[3])
        : "r"(a[0]), "r"(a[1]), "r"(a[2]), "r"(a[3]), "r"(b0), "r"(b1));
}

// ---------------- kernel 1: QKV projection + packing -------------------------
__global__ __launch_bounds__(256) void qkv_kernel(
    const float* __restrict__ x,
    const float* __restrict__ Wq, const float* __restrict__ bq,
    const float* __restrict__ Wk, const float* __restrict__ bk,
    const float* __restrict__ Wv, const float* __restrict__ bv)
{
    __shared__ float Xs[64][33];
    __shared__ float Ws[64][33];
    const float* Wm; const float* bm;
    if (blockIdx.z == 0)      { Wm=Wq; bm=bq; }
    else if (blockIdx.z == 1) { Wm=Wk; bm=bk; }
    else                      { Wm=Wv; bm=bv; }

    const int m0 = blockIdx.y*64, n0 = blockIdx.x*64;
    const int tid = threadIdx.x, tx = tid & 15, ty = tid >> 4;
    float acc[4][4] = {};

    for (int k0 = 0; k0 < DD; k0 += 32) {
        for (int idx = tid; idx < 2048; idx += 256) {
            int r = idx >> 5, c = idx & 31;
            Xs[r][c] = x[(size_t)(m0+r)*DD + k0 + c];
            Ws[r][c] = Wm[(size_t)(n0+r)*DD + k0 + c];
        }
        __syncthreads();
        #pragma unroll
        for (int kk = 0; kk < 32; kk++) {
            float a[4], w[4];
            #pragma unroll
            for (int i=0;i<4;i++) a[i] = Xs[ty*4+i][kk];
            #pragma unroll
            for (int j=0;j<4;j++) w[j] = Ws[tx*4+j][kk];
            #pragma unroll
            for (int i=0;i<4;i++)
                #pragma unroll
                for (int j=0;j<4;j++) acc[i][j] += a[i]*w[j];
        }
        __syncthreads();
    }
    const float SCALE = 0.17677669529663687f;  // 1/sqrt(32)
    #pragma unroll
    for (int i=0;i<4;i++){
        int m = m0 + ty*4 + i;
        int b = m >> 11, l = m & (LL-1);
        #pragma unroll
        for (int j=0;j<4;j++){
            int n = n0 + tx*4 + j;
            int h = n >> 5, d = n & 31;
            float v = acc[i][j] + bm[n];
            size_t row = (size_t)(b*HH + h)*LL + l;
            if (blockIdx.z == 0) {
                float sv = v * SCALE;
                __nv_bfloat16 hi = __float2bfloat16(sv);
                g_Q16[row*64 + d]      = hi;
                g_Q16[row*64 + 32 + d] = __float2bfloat16(sv - __bfloat162float(hi));
            } else if (blockIdx.z == 1) {
                __nv_bfloat16 hi = __float2bfloat16(v);
                g_K16[row*64 + d]      = hi;
                g_K16[row*64 + 32 + d] = __float2bfloat16(v - __bfloat162float(hi));
            } else {
                g_V[row*HD + d] = v;
            }
        }
    }
}

// ---------------- kernel 1b: V transpose + f16 hi/lo -------------------------
__global__ __launch_bounds__(256) void vt_kernel()
{
    __shared__ float Vsm[128][33];
    const int bh = blockIdx.x, l0 = blockIdx.y*128;
    const int tid = threadIdx.x;
    for (int idx = tid; idx < 128*32; idx += 256) {
        int i = idx >> 5, d = idx & 31;
        Vsm[i][d] = g_V[((size_t)bh*LL + l0 + i)*HD + d];
    }
    __syncthreads();
    for (int idx = tid; idx < 32*128; idx += 256) {
        int d = idx >> 7, i = idx & 127;
        float v = Vsm[i][d];
        __half hi = __float2half_rn(v);
        __half lo = __float2half_rn(v - __half2float(hi));
        g_VT16[((size_t)bh*64 + d)*LL + l0 + i]      = hi;
        g_VT16[((size_t)bh*64 + 32 + d)*LL + l0 + i] = lo;
    }
}

// ---------------- kernel 2: prior tables -------------------------------------
__global__ void prior_e_kernel(const float* __restrict__ u)
{
    int h = blockIdx.x;
    float uv = u[h];
    float c = 0.5f / (uv*uv + 1e-6f);
    for (int d = threadIdx.x; d < LL; d += blockDim.x) {
        float fd = (float)d;
        g_E[h*LL + d] = expf(-(fd*fd) * c);
    }
}
__global__ __launch_bounds__(256) void prior_rs_kernel()
{
    __shared__ float Es[LL];
    int h = blockIdx.y;
    for (int i = threadIdx.x; i < LL; i += 256) Es[i] = g_E[h*LL + i];
    __syncthreads();
    int q = blockIdx.x*256 + threadIdx.x;
    float s = 0.f;
    for (int k = 0; k < LL; k++) s += Es[abs(q - k)];
    g_rs[h*LL + q] = s;
}

// ---------------- kernel 3: FUSED scores+softmax+disc+AV via mma.sync --------
// SMEM (float units):
//  [0, 32960)       Srow 16 x SPITCH (fp32 scores, then in-place normalized f16)
//  [32960, 49600)   R2: P1 K-chunks (Khi 256x20 | Klo 256x20 u32)
//                       P4 V-chunks (Vhi 32x260 | Vlo 32x260 u32)
//  [49600, 51648)   Es (2048)  -> reused as Op (4x16x32) after disc
//  [51648, 52176)   Qst 16x33 u32 pairs
//  [52176, 52192)   irs
#define SMF_R2   32960
#define SMF_ES   49600
#define SMF_QST  51648
#define SMF_IRS  52176
#define SMF_TOT  52192
#define SMF_BYTES (SMF_TOT*4)

__global__ __launch_bounds__(512,1) void attn_fused_kernel()
{
    extern __shared__ float sm[];
    float*    Srow = sm;
    uint32_t* PU   = (uint32_t*)sm;          // half-pair view of Srow (pitch SPITCH)
    uint32_t* R2   = (uint32_t*)(sm + SMF_R2);
    float*    Es   = sm + SMF_ES;
    float*    Op   = sm + SMF_ES;             // overlay (after disc)
    uint32_t* Qst  = (uint32_t*)(sm + SMF_QST);
    float*    irs  = sm + SMF_IRS;

    const int tid = threadIdx.x, wid = tid >> 5, lane = tid & 31;
    const int gr = lane >> 2, kp = lane & 3;
    const int qt = blockIdx.x, bh = blockIdx.y;
    const int b = bh >> 3, h = bh & 7, q0 = qt * QT;

    // ---- phase 0 -----------------------------------------------------------
    {   // Q pairs (16 rows x 32 u32: hi 0..15 | lo 16..31)
        int r = tid >> 5, c = tid & 31;
        Qst[r*33 + c] = ((const uint32_t*)g_Q16)[((size_t)bh*LL + q0 + r)*32 + c];
    }
    for (int i = tid; i < LL; i += 512) Es[i] = g_E[h*LL + i];
    if (tid < QT) irs[tid] = 1.0f / (g_rs[h*LL + q0 + tid] + 1e-6f);
    __syncthreads();

    // Q A-fragments: [prec][kstep][4]
    uint32_t qa[2][2][4];
    #pragma unroll
    for (int p = 0; p < 2; p++){
        int base = p*16;
        #pragma unroll
        for (int s = 0; s < 2; s++){
            qa[p][s][0] = Qst[ gr    *33 + base + kp     + 8*s];
            qa[p][s][1] = Qst[(gr+8) *33 + base + kp     + 8*s];
            qa[p][s][2] = Qst[ gr    *33 + base + kp + 4 + 8*s];
            qa[p][s][3] = Qst[(gr+8) *33 + base + kp + 4 + 8*s];
        }
    }

    // ---- phase 1: scores, 8 chunks of 256 keys ------------------------------
    const uint4* Gk4 = (const uint4*)g_K16;
    for (int kc = 0; kc < 8; kc++) {
        __syncthreads();
        // stage Khi/Klo chunk into R2 (pitch 20 u32 per key)
        #pragma unroll
        for (int j = 0; j < 2; j++) {
            int u = tid + j*512;            // 1024 uint4 per precision
            int key = u >> 2, q4 = u & 3;
            size_t row = (size_t)bh*LL + kc*256 + key;
            uint4 vh = Gk4[row*8 + q4];
            uint4 vl = Gk4[row*8 + 4 + q4];
            *(uint4*)(R2 + key*20 + q4*4)        = vh;
            *(uint4*)(R2 + 5120 + key*20 + q4*4) = vl;
        }
        __syncthreads();
        #pragma unroll
        for (int t = 0; t < 2; t++) {
            int nt = wid*2 + t;             // n-tile within chunk (0..31)
            int n0 = nt*8;
            float c[4] = {0.f,0.f,0.f,0.f};
            #pragma unroll
            for (int s = 0; s < 2; s++) {
                uint32_t bh0 = R2[(n0+gr)*20 + kp     + 8*s];
                uint32_t bh1 = R2[(n0+gr)*20 + kp + 4 + 8*s];
                uint32_t bl0 = R2[5120 + (n0+gr)*20 + kp     + 8*s];
                uint32_t bl1 = R2[5120 + (n0+gr)*20 + kp + 4 + 8*s];
                mma_bf16(c, qa[0][s], bh0, bh1);   // hi*hi
                mma_bf16(c, qa[0][s], bl0, bl1);   // hi*lo
                mma_bf16(c, qa[1][s], bh0, bh1);   // lo*hi
            }
            int col = kc*256 + n0 + kp*2;
            *(float2*)&Srow[ gr   *SPITCH + col] = make_float2(c[0], c[1]);
            *(float2*)&Srow[(gr+8)*SPITCH + col] = make_float2(c[2], c[3]);
        }
    }
    __syncthreads();

    // ---- phase 2: softmax, warp per row; in-place convert to normalized f16 -
    {
        float* R = Srow + wid*SPITCH;
        float m = -3.4e38f;
        #pragma unroll 8
        for (int k = lane; k < LL; k += 32) m = fmaxf(m, R[k]);
        m = warpMax(m);
        float s = 0.f;
        #pragma unroll 8
        for (int k = lane; k < LL; k += 32) {
            float e = __expf(R[k] - m);
            R[k] = e;
            s += e;
        }
        s = warpSum(s);
        float iv = 1.0f / s;
        // in-place fp32 -> f16: float4 read, syncwarp, half4 write (safe order)
        uint2* W2 = (uint2*)R;
        const float4* R4 = (const float4*)R;
        #pragma unroll
        for (int i = 0; i < 16; i++) {
            float4 v = R4[i*32 + lane];
            __syncwarp();
            __half2 p0 = __floats2half2_rn(v.x*iv, v.y*iv);
            __half2 p1 = __floats2half2_rn(v.z*iv, v.w*iv);
            uint2 o;
            o.x = *(const uint32_t*)&p0;
            o.y = *(const uint32_t*)&p1;
            W2[i*32 + lane] = o;
        }
    }
    __syncthreads();

    // ---- phase 3: discrepancy partials (reads normalized f16) ---------------
    {
        const __half* Ph = (const __half*)Srow;
        size_t pbase = (((size_t)(b*HH + h))*128 + qt) * LL;
        #pragma unroll
        for (int t = 0; t < 4; t++) {
            int k = tid + t*512;
            float acc = 0.f;
            #pragma unroll
            for (int q = 0; q < QT; q++) {
                float a = __half2float(Ph[q*PHPITCH + k]);
                float p = Es[abs(q0 + q - k)] * irs[q];
                acc += fabsf(a - p);
            }
            g_dpart[pbase + k] = acc;
        }
    }

    // ---- phase 4: O = P @ V via mma.f16 -------------------------------------
    {
        const int nt = wid & 3, seg = wid >> 2;   // 4 d-tiles x 4 k-segments
        const uint4* Gv4 = (const uint4*)g_VT16;
        uint32_t* Vhi = R2;          // [32 d][260] u32 pairs along l
        uint32_t* Vlo = R2 + 8320;
        float c[4] = {0.f,0.f,0.f,0.f};

        for (int ch = 0; ch < 4; ch++) {          // 512 l per chunk
            __syncthreads();                      // prior chunk reads / disc done
            #pragma unroll
            for (int j = 0; j < 4; j++) {         // 2048 uint4 per precision
                int u = tid + j*512;
                int d = u >> 6, p4 = u & 63;
                uint4 vh = Gv4[((size_t)bh*64 + d)*256      + ch*64 + p4];
                uint4 vl = Gv4[((size_t)bh*64 + 32 + d)*256 + ch*64 + p4];
                *(uint4*)(Vhi + d*260 + p4*4) = vh;
                *(uint4*)(Vlo + d*260 + p4*4) = vl;
            }
            __syncthreads();
            #pragma unroll
            for (int ks = 0; ks < 8; ks++) {      // 128 l per sub-segment
                int kg2 = ch*256 + seg*64 + ks*8; // u32 pair offset (global k/2)
                uint32_t a[4];
                a[0] = PU[ gr   *SPITCH + kg2 + kp];
                a[1] = PU[(gr+8)*SPITCH + kg2 + kp];
                a[2] = PU[ gr   *SPITCH + kg2 + kp + 4];
                a[3] = PU[(gr+8)*SPITCH + kg2 + kp + 4];
                int kb = seg*64 + ks*8;
                uint32_t bh0 = Vhi[(nt*8+gr)*260 + kb + kp];
                uint32_t bh1 = Vhi[(nt*8+gr)*260 + kb + kp + 4];
                uint32_t bl0 = Vlo[(nt*8+gr)*260 + kb + kp];
                uint32_t bl1 = Vlo[(nt*8+gr)*260 + kb + kp + 4];
                mma_f16(c, a, bh0, bh1);
                mma_f16(c, a, bl0, bl1);
            }
        }
        __syncthreads();                          // Es no longer needed -> Op
        int dcol = nt*8 + kp*2;
        Op[seg*512 +  gr   *32 + dcol]     = c[0];
        Op[seg*512 +  gr   *32 + dcol + 1] = c[1];
        Op[seg*512 + (gr+8)*32 + dcol]     = c[2];
        Op[seg*512 + (gr+8)*32 + dcol + 1] = c[3];
    }
    __syncthreads();
    {
        int q = tid >> 5, d = tid & 31;
        float s = Op[q*32 + d] + Op[512 + q*32 + d]
                + Op[1024 + q*32 + d] + Op[1536 + q*32 + d];
        g_O[((size_t)bh*LL + q0 + q)*HD + d] = s;
    }
}

// ---------------- kernel 4: discrepancy reduce (2-stage) ----------------------
__global__ void disc_reduce1_kernel()
{
    int k = blockIdx.x*256 + threadIdx.x;    // < B*L
    int seg = blockIdx.y;                    // 16 segments of 64 partials
    int b = k >> 11, kk = k & (LL-1);
    const float* base = g_dpart + (size_t)b*HH*128*LL + kk;
    float s = 0.f;
    #pragma unroll 8
    for (int p = seg*64; p < seg*64 + 64; p++) s += base[(size_t)p*LL];
    g_dpart2[seg*BB*LL + k] = s;
}
__global__ void disc_reduce2_kernel(float* __restrict__ dout)
{
    int idx = blockIdx.x*256 + threadIdx.x;  // < B*L
    float s = 0.f;
    #pragma unroll
    for (int seg = 0; seg < 16; seg++) s += g_dpart2[seg*BB*LL + idx];
    dout[idx] = s * (1.0f/(HH*(float)LL));
}

// ---------------- kernel 5: out projection ------------------------------------
__global__ __launch_bounds__(256) void outproj_kernel(
    const float* __restrict__ Wo, const float* __restrict__ bo,
    float* __restrict__ out)
{
    __shared__ float Xs[64][33];
    __shared__ float Ws[64][33];
    const int m0 = blockIdx.y*64, n0 = blockIdx.x*64;
    const int tid = threadIdx.x, tx = tid & 15, ty = tid >> 4;
    float acc[4][4] = {};

    for (int k0 = 0; k0 < DD; k0 += 32) {
        int h = k0 >> 5;
        for (int idx = tid; idx < 2048; idx += 256) {
            int r = idx >> 5, c = idx & 31;
            int m = m0 + r;
            int b = m >> 11, l = m & (LL-1);
            Xs[r][c] = g_O[(((size_t)(b*HH + h))*LL + l)*HD + c];
            Ws[r][c] = Wo[(size_t)(n0+r)*DD + k0 + c];
        }
        __syncthreads();
        #pragma unroll
        for (int kk = 0; kk < 32; kk++) {
            float a[4], w[4];
            #pragma unroll
            for (int i=0;i<4;i++) a[i] = Xs[ty*4+i][kk];
            #pragma unroll
            for (int j=0;j<4;j++) w[j] = Ws[tx*4+j][kk];
            #pragma unroll
            for (int i=0;i<4;i++)
                #pragma unroll
                for (int j=0;j<4;j++) acc[i][j] += a[i]*w[j];
        }
        __syncthreads();
    }
    #pragma unroll
    for (int i=0;i<4;i++){
        int m = m0 + ty*4 + i;
        #pragma unroll
        for (int j=0;j<4;j++){
            int n = n0 + tx*4 + j;
            out[(size_t)m*DD + n] = acc[i][j] + bo[n];
        }
    }
}

// ---------------- launch --------------------------------------------------------
extern "C" void kernel_launch(void* const* d_in, const int* in_sizes, int n_in,
                              void* d_out, int out_size)
{
    const float* x  = (const float*)d_in[0];
    const float* Wq = (const float*)d_in[1];
    const float* bq = (const float*)d_in[2];
    const float* Wk = (const float*)d_in[3];
    const float* bk = (const float*)d_in[4];
    const float* Wv = (const float*)d_in[5];
    const float* bv = (const float*)d_in[6];
    const float* u  = (const float*)d_in[7];
    const float* Wo = (const float*)d_in[8];
    const float* bo = (const float*)d_in[9];
    float* out = (float*)d_out;

    cudaFuncSetAttribute(attn_fused_kernel,
                         cudaFuncAttributeMaxDynamicSharedMemorySize, SMF_BYTES);

    qkv_kernel<<<dim3(DD/64, (BB*LL)/64, 3), 256>>>(x, Wq, bq, Wk, bk, Wv, bv);
    vt_kernel<<<dim3(BH, LL/128), 256>>>();
    prior_e_kernel<<<HH, 256>>>(u);
    prior_rs_kernel<<<dim3(LL/256, HH), 256>>>();
    attn_fused_kernel<<<dim3(LL/QT, BH), 512, SMF_BYTES>>>();
    disc_reduce1_kernel<<<dim3((BB*LL)/256, 16), 256>>>();
    disc_reduce2_kernel<<<(BB*LL)/256, 256>>>(out + (size_t)BB*LL*DD);
    outproj_kernel<<<dim3(DD/64, (BB*LL)/64), 256>>>(Wo, bo, out);
}

// round 8
// speedup vs baseline: 1.7139x; 1.0604x over previous
#include <cuda_runtime.h>
#include <cuda_bf16.h>
#include <cuda_fp16.h>
#include <math.h>
#include <stdint.h>

#define BB 2
#define LL 2048
#define DD 256
#define HH 8
#define HD 32
#define BH (BB*HH)
#define QT 16
#define SPITCH 2060
#define PHPITCH (SPITCH*2)

// ---------------- scratch (device globals; no allocation allowed) ----------
__device__ float         g_V  [(size_t)BH*LL*HD];
__device__ float         g_O  [(size_t)BH*LL*HD];
__device__ __nv_bfloat16 g_Q16[(size_t)BH*LL*64];    // rows [Qhi d0..31 | Qlo d0..31] (scaled)
__device__ __nv_bfloat16 g_K16[(size_t)BH*LL*64];    // rows [Khi | Klo]
__device__ __half        g_VT16[(size_t)BH*64*LL];   // [bh][hi d / 32+lo d][l]
__device__ float         g_E  [HH*LL];
__device__ float         g_rs [HH*LL];
__device__ float         g_dpart[(size_t)BB*HH*128*LL];
__device__ float         g_dpart2[16*BB*LL];

// ---------------- helpers ----------------------------------------------------
__device__ __forceinline__ float warpMax(float v){
    #pragma unroll
    for (int o=16;o;o>>=1) v = fmaxf(v, __shfl_xor_sync(0xffffffffu, v, o));
    return v;
}
__device__ __forceinline__ float warpSum(float v){
    #pragma unroll
    for (int o=16;o;o>>=1) v += __shfl_xor_sync(0xffffffffu, v, o);
    return v;
}
__device__ __forceinline__ void mma_bf16(float* c, const uint32_t* a,
                                         uint32_t b0, uint32_t b1){
    asm volatile(
        "mma.sync.aligned.m16n8k16.row.col.f32.bf16.bf16.f32 "
        "{%0,%1,%2,%3}, {%4,%5,%6,%7}, {%8,%9}, {%0,%1,%2,%3};"
        : "+f"(c[0]), "+f"(c[1]), "+f"(c[2]), "+f"(c[3])
        : "r"(a[0]), "r"(a[1]), "r"(a[2]), "r"(a[3]), "r"(b0), "r"(b1));
}
__device__ __forceinline__ void mma_f16(float* c, const uint32_t* a,
                                        uint32_t b0, uint32_t b1){
    asm volatile(
        "mma.sync.aligned.m16n8k16.row.col.f32.f16.f16.f32 "
        "{%0,%1,%2,%3}, {%4,%5,%6,%7}, {%8,%9}, {%0,%1,%2,%3};"
        : "+f"(c[0]), "+f"(c[1]), "+f"(c[2]), "+f"(c[3])
        : "r"(a[0]), "r"(a[1]), "r"(a[2]), "r"(a[3]), "r"(b0), "r"(b1));
}

// ---------------- kernel 1: QKV projection via mma (bf16 3-product split) ----
// block 128m x 64n, 256 threads (8 warps, each 16m x 64n). K chunks of 64.
#define LK_XL (128*33)
#define LK_WH (2*128*33)
#define LK_WL (2*128*33 + 64*33)
#define LK_TOT (2*128*33 + 2*64*33)     // 12672 u32 = 50688 B

__global__ __launch_bounds__(256) void qkv_mma_kernel(
    const float* __restrict__ x,
    const float* __restrict__ Wq, const float* __restrict__ bq,
    const float* __restrict__ Wk, const float* __restrict__ bk,
    const float* __restrict__ Wv, const float* __restrict__ bv)
{
    extern __shared__ uint32_t usm[];
    uint32_t* Xh = usm;
    uint32_t* Xl = usm + LK_XL;
    uint32_t* Wh = usm + LK_WH;
    uint32_t* Wl = usm + LK_WL;

    const float* Wm; const float* bm;
    if (blockIdx.z == 0)      { Wm=Wq; bm=bq; }
    else if (blockIdx.z == 1) { Wm=Wk; bm=bk; }
    else                      { Wm=Wv; bm=bv; }

    const int m0 = blockIdx.y*128, n0 = blockIdx.x*64;
    const int tid = threadIdx.x, wid = tid>>5, lane = tid&31;
    const int gr = lane>>2, kp = lane&3;

    float c[8][4] = {};
    for (int kc = 0; kc < 4; kc++) {
        __syncthreads();
        #pragma unroll
        for (int j = 0; j < 16; j++) {          // X: 128 rows x 32 pairs
            int u2 = tid + j*256;
            int r = u2 >> 5, cc = u2 & 31;
            float2 v = *(const float2*)&x[(size_t)(m0+r)*DD + kc*64 + cc*2];
            __nv_bfloat162 hb = __floats2bfloat162_rn(v.x, v.y);
            __nv_bfloat162 lb = __floats2bfloat162_rn(
                v.x - __bfloat162float(hb.x), v.y - __bfloat162float(hb.y));
            Xh[r*33 + cc] = *(const uint32_t*)&hb;
            Xl[r*33 + cc] = *(const uint32_t*)&lb;
        }
        #pragma unroll
        for (int j = 0; j < 8; j++) {           // W: 64 rows x 32 pairs
            int u2 = tid + j*256;
            int r = u2 >> 5, cc = u2 & 31;
            float2 v = *(const float2*)&Wm[(size_t)(n0+r)*DD + kc*64 + cc*2];
            __nv_bfloat162 hb = __floats2bfloat162_rn(v.x, v.y);
            __nv_bfloat162 lb = __floats2bfloat162_rn(
                v.x - __bfloat162float(hb.x), v.y - __bfloat162float(hb.y));
            Wh[r*33 + cc] = *(const uint32_t*)&hb;
            Wl[r*33 + cc] = *(const uint32_t*)&lb;
        }
        __syncthreads();
        #pragma unroll
        for (int s = 0; s < 4; s++) {
            const int mb = wid*16;
            uint32_t ah[4], al[4];
            ah[0] = Xh[(mb+gr  )*33 + s*8 + kp];
            ah[1] = Xh[(mb+gr+8)*33 + s*8 + kp];
            ah[2] = Xh[(mb+gr  )*33 + s*8 + kp + 4];
            ah[3] = Xh[(mb+gr+8)*33 + s*8 + kp + 4];
            al[0] = Xl[(mb+gr  )*33 + s*8 + kp];
            al[1] = Xl[(mb+gr+8)*33 + s*8 + kp];
            al[2] = Xl[(mb+gr  )*33 + s*8 + kp + 4];
            al[3] = Xl[(mb+gr+8)*33 + s*8 + kp + 4];
            #pragma unroll
            for (int nt = 0; nt < 8; nt++) {
                uint32_t bh0 = Wh[(nt*8+gr)*33 + s*8 + kp];
                uint32_t bh1 = Wh[(nt*8+gr)*33 + s*8 + kp + 4];
                uint32_t bl0 = Wl[(nt*8+gr)*33 + s*8 + kp];
                uint32_t bl1 = Wl[(nt*8+gr)*33 + s*8 + kp + 4];
                mma_bf16(c[nt], ah, bh0, bh1);   // hi*hi
                mma_bf16(c[nt], ah, bl0, bl1);   // hi*lo
                mma_bf16(c[nt], al, bh0, bh1);   // lo*hi
            }
        }
    }
    const float SCALE = 0.17677669529663687f;    // 1/sqrt(32)
    #pragma unroll
    for (int nt = 0; nt < 8; nt++) {
        #pragma unroll
        for (int hf = 0; hf < 2; hf++) {
            int m = m0 + wid*16 + gr + hf*8;
            int b = m >> 11, l = m & (LL-1);
            #pragma unroll
            for (int e = 0; e < 2; e++) {
                int n = n0 + nt*8 + kp*2 + e;
                float v = c[nt][hf*2 + e] + bm[n];
                int h = n >> 5, d = n & 31;
                size_t row = (size_t)(b*HH + h)*LL + l;
                if (blockIdx.z == 0) {
                    float sv = v * SCALE;
                    __nv_bfloat16 hi = __float2bfloat16(sv);
                    g_Q16[row*64 + d]      = hi;
                    g_Q16[row*64 + 32 + d] = __float2bfloat16(sv - __bfloat162float(hi));
                } else if (blockIdx.z == 1) {
                    __nv_bfloat16 hi = __float2bfloat16(v);
                    g_K16[row*64 + d]      = hi;
                    g_K16[row*64 + 32 + d] = __float2bfloat16(v - __bfloat162float(hi));
                } else {
                    g_V[row*HD + d] = v;
                }
            }
        }
    }
}

// ---------------- kernel 1b: V transpose + f16 hi/lo -------------------------
__global__ __launch_bounds__(256) void vt_kernel()
{
    __shared__ float Vsm[128][33];
    const int bh = blockIdx.x, l0 = blockIdx.y*128;
    const int tid = threadIdx.x;
    for (int idx = tid; idx < 128*32; idx += 256) {
        int i = idx >> 5, d = idx & 31;
        Vsm[i][d] = g_V[((size_t)bh*LL + l0 + i)*HD + d];
    }
    __syncthreads();
    for (int idx = tid; idx < 32*128; idx += 256) {
        int d = idx >> 7, i = idx & 127;
        float v = Vsm[i][d];
        __half hi = __float2half_rn(v);
        __half lo = __float2half_rn(v - __half2float(hi));
        g_VT16[((size_t)bh*64 + d)*LL + l0 + i]      = hi;
        g_VT16[((size_t)bh*64 + 32 + d)*LL + l0 + i] = lo;
    }
}

// ---------------- kernel 2: prior tables via prefix sum ----------------------
// rs[q] = sum_k E[|q-k|] = P[q] + P[L-1-q] - E[0],  P = inclusive prefix of E.
__global__ __launch_bounds__(256) void prior_kernel(const float* __restrict__ u)
{
    __shared__ float Es[LL];
    __shared__ float Ps[LL];
    __shared__ float part[256];
    const int h = blockIdx.x, tid = threadIdx.x;
    float uv = u[h];
    float cc = 0.5f / (uv*uv + 1e-6f);
    #pragma unroll
    for (int j = 0; j < 8; j++) {
        int d = tid + j*256;
        float fd = (float)d;
        float e = expf(-(fd*fd)*cc);
        Es[d] = e;
        g_E[h*LL + d] = e;
    }
    __syncthreads();
    float s = 0.f;
    #pragma unroll
    for (int i = 0; i < 8; i++) s += Es[tid*8 + i];
    part[tid] = s;
    __syncthreads();
    if (tid == 0) {
        float run = 0.f;
        for (int i = 0; i < 256; i++) { run += part[i]; part[i] = run; }
    }
    __syncthreads();
    float run = (tid == 0) ? 0.f : part[tid-1];
    #pragma unroll
    for (int i = 0; i < 8; i++) {
        run += Es[tid*8 + i];
        Ps[tid*8 + i] = run;
    }
    __syncthreads();
    float e0 = Es[0];
    #pragma unroll
    for (int j = 0; j < 8; j++) {
        int q = tid + j*256;
        g_rs[h*LL + q] = Ps[q] + Ps[LL-1-q] - e0;
    }
}

// ---------------- kernel 3: FUSED scores+softmax+disc+AV via mma.sync --------
#define SMF_R2   32960
#define SMF_ES   49600
#define SMF_QST  51648
#define SMF_IRS  52176
#define SMF_TOT  52192
#define SMF_BYTES (SMF_TOT*4)

__global__ __launch_bounds__(512,1) void attn_fused_kernel()
{
    extern __shared__ float sm[];
    float*    Srow = sm;
    uint32_t* PU   = (uint32_t*)sm;
    uint32_t* R2   = (uint32_t*)(sm + SMF_R2);
    float*    Es   = sm + SMF_ES;
    float*    Op   = sm + SMF_ES;
    uint32_t* Qst  = (uint32_t*)(sm + SMF_QST);
    float*    irs  = sm + SMF_IRS;

    const int tid = threadIdx.x, wid = tid >> 5, lane = tid & 31;
    const int gr = lane >> 2, kp = lane & 3;
    const int qt = blockIdx.x, bh = blockIdx.y;
    const int b = bh >> 3, h = bh & 7, q0 = qt * QT;

    {
        int r = tid >> 5, c = tid & 31;
        Qst[r*33 + c] = ((const uint32_t*)g_Q16)[((size_t)bh*LL + q0 + r)*32 + c];
    }
    for (int i = tid; i < LL; i += 512) Es[i] = g_E[h*LL + i];
    if (tid < QT) irs[tid] = 1.0f / (g_rs[h*LL + q0 + tid] + 1e-6f);
    __syncthreads();

    uint32_t qa[2][2][4];
    #pragma unroll
    for (int p = 0; p < 2; p++){
        int base = p*16;
        #pragma unroll
        for (int s = 0; s < 2; s++){
            qa[p][s][0] = Qst[ gr    *33 + base + kp     + 8*s];
            qa[p][s][1] = Qst[(gr+8) *33 + base + kp     + 8*s];
            qa[p][s][2] = Qst[ gr    *33 + base + kp + 4 + 8*s];
            qa[p][s][3] = Qst[(gr+8) *33 + base + kp + 4 + 8*s];
        }
    }

    const uint4* Gk4 = (const uint4*)g_K16;
    for (int kc = 0; kc < 8; kc++) {
        __syncthreads();
        #pragma unroll
        for (int j = 0; j < 2; j++) {
            int u2 = tid + j*512;
            int key = u2 >> 2, q4 = u2 & 3;
            size_t row = (size_t)bh*LL + kc*256 + key;
            uint4 vh = Gk4[row*8 + q4];
            uint4 vl = Gk4[row*8 + 4 + q4];
            *(uint4*)(R2 + key*20 + q4*4)        = vh;
            *(uint4*)(R2 + 5120 + key*20 + q4*4) = vl;
        }
        __syncthreads();
        #pragma unroll
        for (int t = 0; t < 2; t++) {
            int nt = wid*2 + t;
            int n0 = nt*8;
            float c[4] = {0.f,0.f,0.f,0.f};
            #pragma unroll
            for (int s = 0; s < 2; s++) {
                uint32_t bh0 = R2[(n0+gr)*20 + kp     + 8*s];
                uint32_t bh1 = R2[(n0+gr)*20 + kp + 4 + 8*s];
                uint32_t bl0 = R2[5120 + (n0+gr)*20 + kp     + 8*s];
                uint32_t bl1 = R2[5120 + (n0+gr)*20 + kp + 4 + 8*s];
                mma_bf16(c, qa[0][s], bh0, bh1);
                mma_bf16(c, qa[0][s], bl0, bl1);
                mma_bf16(c, qa[1][s], bh0, bh1);
            }
            int col = kc*256 + n0 + kp*2;
            *(float2*)&Srow[ gr   *SPITCH + col] = make_float2(c[0], c[1]);
            *(float2*)&Srow[(gr+8)*SPITCH + col] = make_float2(c[2], c[3]);
        }
    }
    __syncthreads();

    {
        float* R = Srow + wid*SPITCH;
        float m = -3.4e38f;
        #pragma unroll 8
        for (int k = lane; k < LL; k += 32) m = fmaxf(m, R[k]);
        m = warpMax(m);
        float s = 0.f;
        #pragma unroll 8
        for (int k = lane; k < LL; k += 32) {
            float e = __expf(R[k] - m);
            R[k] = e;
            s += e;
        }
        s = warpSum(s);
        float iv = 1.0f / s;
        uint2* W2 = (uint2*)R;
        const float4* R4 = (const float4*)R;
        #pragma unroll
        for (int i = 0; i < 16; i++) {
            float4 v = R4[i*32 + lane];
            __syncwarp();
            __half2 p0 = __floats2half2_rn(v.x*iv, v.y*iv);
            __half2 p1 = __floats2half2_rn(v.z*iv, v.w*iv);
            uint2 o;
            o.x = *(const uint32_t*)&p0;
            o.y = *(const uint32_t*)&p1;
            W2[i*32 + lane] = o;
        }
    }
    __syncthreads();

    {
        const __half* Ph = (const __half*)Srow;
        size_t pbase = (((size_t)(b*HH + h))*128 + qt) * LL;
        #pragma unroll
        for (int t = 0; t < 4; t++) {
            int k = tid + t*512;
            float acc = 0.f;
            #pragma unroll
            for (int q = 0; q < QT; q++) {
                float a = __half2float(Ph[q*PHPITCH + k]);
                float p = Es[abs(q0 + q - k)] * irs[q];
                acc += fabsf(a - p);
            }
            g_dpart[pbase + k] = acc;
        }
    }

    {
        const int nt = wid & 3, seg = wid >> 2;
        const uint4* Gv4 = (const uint4*)g_VT16;
        uint32_t* Vhi = R2;
        uint32_t* Vlo = R2 + 8320;
        float c[4] = {0.f,0.f,0.f,0.f};

        for (int ch = 0; ch < 4; ch++) {
            __syncthreads();
            #pragma unroll
            for (int j = 0; j < 4; j++) {
                int u2 = tid + j*512;
                int d = u2 >> 6, p4 = u2 & 63;
                uint4 vh = Gv4[((size_t)bh*64 + d)*256      + ch*64 + p4];
                uint4 vl = Gv4[((size_t)bh*64 + 32 + d)*256 + ch*64 + p4];
                *(uint4*)(Vhi + d*260 + p4*4) = vh;
                *(uint4*)(Vlo + d*260 + p4*4) = vl;
            }
            __syncthreads();
            #pragma unroll
            for (int ks = 0; ks < 8; ks++) {
                int kg2 = ch*256 + seg*64 + ks*8;
                uint32_t a[4];
                a[0] = PU[ gr   *SPITCH + kg2 + kp];
                a[1] = PU[(gr+8)*SPITCH + kg2 + kp];
                a[2] = PU[ gr   *SPITCH + kg2 + kp + 4];
                a[3] = PU[(gr+8)*SPITCH + kg2 + kp + 4];
                int kb = seg*64 + ks*8;
                uint32_t bh0 = Vhi[(nt*8+gr)*260 + kb + kp];
                uint32_t bh1 = Vhi[(nt*8+gr)*260 + kb + kp + 4];
                uint32_t bl0 = Vlo[(nt*8+gr)*260 + kb + kp];
                uint32_t bl1 = Vlo[(nt*8+gr)*260 + kb + kp + 4];
                mma_f16(c, a, bh0, bh1);
                mma_f16(c, a, bl0, bl1);
            }
        }
        __syncthreads();
        int dcol = nt*8 + kp*2;
        Op[seg*512 +  gr   *32 + dcol]     = c[0];
        Op[seg*512 +  gr   *32 + dcol + 1] = c[1];
        Op[seg*512 + (gr+8)*32 + dcol]     = c[2];
        Op[seg*512 + (gr+8)*32 + dcol + 1] = c[3];
    }
    __syncthreads();
    {
        int q = tid >> 5, d = tid & 31;
        float s = Op[q*32 + d] + Op[512 + q*32 + d]
                + Op[1024 + q*32 + d] + Op[1536 + q*32 + d];
        g_O[((size_t)bh*LL + q0 + q)*HD + d] = s;
    }
}

// ---------------- kernel 4: discrepancy reduce (2-stage) ----------------------
__global__ void disc_reduce1_kernel()
{
    int k = blockIdx.x*256 + threadIdx.x;
    int seg = blockIdx.y;
    int b = k >> 11, kk = k & (LL-1);
    const float* base = g_dpart + (size_t)b*HH*128*LL + kk;
    float s = 0.f;
    #pragma unroll 8
    for (int p = seg*64; p < seg*64 + 64; p++) s += base[(size_t)p*LL];
    g_dpart2[seg*BB*LL + k] = s;
}
__global__ void disc_reduce2_kernel(float* __restrict__ dout)
{
    int idx = blockIdx.x*256 + threadIdx.x;
    float s = 0.f;
    #pragma unroll
    for (int seg = 0; seg < 16; seg++) s += g_dpart2[seg*BB*LL + idx];
    dout[idx] = s * (1.0f/(HH*(float)LL));
}

// ---------------- kernel 5: out projection via mma ---------------------------
__global__ __launch_bounds__(256) void outproj_mma_kernel(
    const float* __restrict__ Wo, const float* __restrict__ bo,
    float* __restrict__ out)
{
    extern __shared__ uint32_t usm[];
    uint32_t* Xh = usm;
    uint32_t* Xl = usm + LK_XL;
    uint32_t* Wh = usm + LK_WH;
    uint32_t* Wl = usm + LK_WL;

    const int m0 = blockIdx.y*128, n0 = blockIdx.x*64;
    const int tid = threadIdx.x, wid = tid>>5, lane = tid&31;
    const int gr = lane>>2, kp = lane&3;

    float c[8][4] = {};
    for (int kc = 0; kc < 4; kc++) {
        __syncthreads();
        #pragma unroll
        for (int j = 0; j < 16; j++) {          // X from g_O (head-major gather)
            int u2 = tid + j*256;
            int r = u2 >> 5, cc = u2 & 31;
            int m = m0 + r;
            int b = m >> 11, l = m & (LL-1);
            int k = kc*64 + cc*2;
            int hh = k >> 5, d = k & 31;
            float2 v = *(const float2*)&g_O[(((size_t)(b*HH + hh))*LL + l)*HD + d];
            __nv_bfloat162 hb = __floats2bfloat162_rn(v.x, v.y);
            __nv_bfloat162 lb = __floats2bfloat162_rn(
                v.x - __bfloat162float(hb.x), v.y - __bfloat162float(hb.y));
            Xh[r*33 + cc] = *(const uint32_t*)&hb;
            Xl[r*33 + cc] = *(const uint32_t*)&lb;
        }
        #pragma unroll
        for (int j = 0; j < 8; j++) {
            int u2 = tid + j*256;
            int r = u2 >> 5, cc = u2 & 31;
            float2 v = *(const float2*)&Wo[(size_t)(n0+r)*DD + kc*64 + cc*2];
            __nv_bfloat162 hb = __floats2bfloat162_rn(v.x, v.y);
            __nv_bfloat162 lb = __floats2bfloat162_rn(
                v.x - __bfloat162float(hb.x), v.y - __bfloat162float(hb.y));
            Wh[r*33 + cc] = *(const uint32_t*)&hb;
            Wl[r*33 + cc] = *(const uint32_t*)&lb;
        }
        __syncthreads();
        #pragma unroll
        for (int s = 0; s < 4; s++) {
            const int mb = wid*16;
            uint32_t ah[4], al[4];
            ah[0] = Xh[(mb+gr  )*33 + s*8 + kp];
            ah[1] = Xh[(mb+gr+8)*33 + s*8 + kp];
            ah[2] = Xh[(mb+gr  )*33 + s*8 + kp + 4];
            ah[3] = Xh[(mb+gr+8)*33 + s*8 + kp + 4];
            al[0] = Xl[(mb+gr  )*33 + s*8 + kp];
            al[1] = Xl[(mb+gr+8)*33 + s*8 + kp];
            al[2] = Xl[(mb+gr  )*33 + s*8 + kp + 4];
            al[3] = Xl[(mb+gr+8)*33 + s*8 + kp + 4];
            #pragma unroll
            for (int nt = 0; nt < 8; nt++) {
                uint32_t bh0 = Wh[(nt*8+gr)*33 + s*8 + kp];
                uint32_t bh1 = Wh[(nt*8+gr)*33 + s*8 + kp + 4];
                uint32_t bl0 = Wl[(nt*8+gr)*33 + s*8 + kp];
                uint32_t bl1 = Wl[(nt*8+gr)*33 + s*8 + kp + 4];
                mma_bf16(c[nt], ah, bh0, bh1);
                mma_bf16(c[nt], ah, bl0, bl1);
                mma_bf16(c[nt], al, bh0, bh1);
            }
        }
    }
    #pragma unroll
    for (int nt = 0; nt < 8; nt++) {
        #pragma unroll
        for (int hf = 0; hf < 2; hf++) {
            int m = m0 + wid*16 + gr + hf*8;
            int n = n0 + nt*8 + kp*2;
            float2 o;
            o.x = c[nt][hf*2]     + bo[n];
            o.y = c[nt][hf*2 + 1] + bo[n+1];
            *(float2*)&out[(size_t)m*DD + n] = o;
        }
    }
}

// ---------------- launch --------------------------------------------------------
extern "C" void kernel_launch(void* const* d_in, const int* in_sizes, int n_in,
                              void* d_out, int out_size)
{
    const float* x  = (const float*)d_in[0];
    const float* Wq = (const float*)d_in[1];
    const float* bq = (const float*)d_in[2];
    const float* Wk = (const float*)d_in[3];
    const float* bk = (const float*)d_in[4];
    const float* Wv = (const float*)d_in[5];
    const float* bv = (const float*)d_in[6];
    const float* u  = (const float*)d_in[7];
    const float* Wo = (const float*)d_in[8];
    const float* bo = (const float*)d_in[9];
    float* out = (float*)d_out;

    cudaFuncSetAttribute(attn_fused_kernel,
                         cudaFuncAttributeMaxDynamicSharedMemorySize, SMF_BYTES);
    cudaFuncSetAttribute(qkv_mma_kernel,
                         cudaFuncAttributeMaxDynamicSharedMemorySize, LK_TOT*4);
    cudaFuncSetAttribute(outproj_mma_kernel,
                         cudaFuncAttributeMaxDynamicSharedMemorySize, LK_TOT*4);

    qkv_mma_kernel<<<dim3(DD/64, (BB*LL)/128, 3), 256, LK_TOT*4>>>(
        x, Wq, bq, Wk, bk, Wv, bv);
    vt_kernel<<<dim3(BH, LL/128), 256>>>();
    prior_kernel<<<HH, 256>>>(u);
    attn_fused_kernel<<<dim3(LL/QT, BH), 512, SMF_BYTES>>>();
    disc_reduce1_kernel<<<dim3((BB*LL)/256, 16), 256>>>();
    disc_reduce2_kernel<<<(BB*LL)/256, 256>>>(out + (size_t)BB*LL*DD);
    outproj_mma_kernel<<<dim3(DD/64, (BB*LL)/128), 256, LK_TOT*4>>>(Wo, bo, out);
}

// round 9
// speedup vs baseline: 1.8895x; 1.1025x over previous
#include <cuda_runtime.h>
#include <cuda_bf16.h>
#include <cuda_fp16.h>
#include <math.h>
#include <stdint.h>

#define BB 2
#define LL 2048
#define DD 256
#define HH 8
#define HD 32
#define BH (BB*HH)
#define QT 16
#define SPITCH 2060
#define PHPITCH (SPITCH*2)

// ---------------- scratch (device globals; no allocation allowed) ----------
__device__ float         g_V  [(size_t)BH*LL*HD];
__device__ float         g_O  [(size_t)BH*LL*HD];
__device__ __nv_bfloat16 g_Q16[(size_t)BH*LL*64];    // rows [Qhi d0..31 | Qlo d0..31] (scaled)
__device__ __nv_bfloat16 g_K16[(size_t)BH*LL*64];    // rows [Khi | Klo]
__device__ __half        g_VT16[(size_t)BH*64*LL];   // [bh][hi d / 32+lo d][l]
__device__ float         g_E  [HH*LL];
__device__ float         g_rs [HH*LL];
__device__ float         g_dpart[(size_t)BB*HH*128*LL];
__device__ float         g_dpart2[16*BB*LL];

// ---------------- helpers ----------------------------------------------------
__device__ __forceinline__ float warpMax(float v){
    #pragma unroll
    for (int o=16;o;o>>=1) v = fmaxf(v, __shfl_xor_sync(0xffffffffu, v, o));
    return v;
}
__device__ __forceinline__ float warpSum(float v){
    #pragma unroll
    for (int o=16;o;o>>=1) v += __shfl_xor_sync(0xffffffffu, v, o);
    return v;
}
__device__ __forceinline__ void mma_bf16(float* c, const uint32_t* a,
                                         uint32_t b0, uint32_t b1){
    asm volatile(
        "mma.sync.aligned.m16n8k16.row.col.f32.bf16.bf16.f32 "
        "{%0,%1,%2,%3}, {%4,%5,%6,%7}, {%8,%9}, {%0,%1,%2,%3};"
        : "+f"(c[0]), "+f"(c[1]), "+f"(c[2]), "+f"(c[3])
        : "r"(a[0]), "r"(a[1]), "r"(a[2]), "r"(a[3]), "r"(b0), "r"(b1));
}
__device__ __forceinline__ void mma_f16(float* c, const uint32_t* a,
                                        uint32_t b0, uint32_t b1){
    asm volatile(
        "mma.sync.aligned.m16n8k16.row.col.f32.f16.f16.f32 "
        "{%0,%1,%2,%3}, {%4,%5,%6,%7}, {%8,%9}, {%0,%1,%2,%3};"
        : "+f"(c[0]), "+f"(c[1]), "+f"(c[2]), "+f"(c[3])
        : "r"(a[0]), "r"(a[1]), "r"(a[2]), "r"(a[3]), "r"(b0), "r"(b1));
}

// ---------------- kernel 1: QKV projection via mma (bf16 3-product split) ----
#define LK_XL (128*33)
#define LK_WH (2*128*33)
#define LK_WL (2*128*33 + 64*33)
#define LK_TOT (2*128*33 + 2*64*33)

__global__ __launch_bounds__(256) void qkv_mma_kernel(
    const float* __restrict__ x,
    const float* __restrict__ Wq, const float* __restrict__ bq,
    const float* __restrict__ Wk, const float* __restrict__ bk,
    const float* __restrict__ Wv, const float* __restrict__ bv)
{
    extern __shared__ uint32_t usm[];
    uint32_t* Xh = usm;
    uint32_t* Xl = usm + LK_XL;
    uint32_t* Wh = usm + LK_WH;
    uint32_t* Wl = usm + LK_WL;

    const float* Wm; const float* bm;
    if (blockIdx.z == 0)      { Wm=Wq; bm=bq; }
    else if (blockIdx.z == 1) { Wm=Wk; bm=bk; }
    else                      { Wm=Wv; bm=bv; }

    const int m0 = blockIdx.y*128, n0 = blockIdx.x*64;
    const int tid = threadIdx.x, wid = tid>>5, lane = tid&31;
    const int gr = lane>>2, kp = lane&3;

    float c[8][4] = {};
    for (int kc = 0; kc < 4; kc++) {
        __syncthreads();
        #pragma unroll
        for (int j = 0; j < 16; j++) {
            int u2 = tid + j*256;
            int r = u2 >> 5, cc = u2 & 31;
            float2 v = *(const float2*)&x[(size_t)(m0+r)*DD + kc*64 + cc*2];
            __nv_bfloat162 hb = __floats2bfloat162_rn(v.x, v.y);
            __nv_bfloat162 lb = __floats2bfloat162_rn(
                v.x - __bfloat162float(hb.x), v.y - __bfloat162float(hb.y));
            Xh[r*33 + cc] = *(const uint32_t*)&hb;
            Xl[r*33 + cc] = *(const uint32_t*)&lb;
        }
        #pragma unroll
        for (int j = 0; j < 8; j++) {
            int u2 = tid + j*256;
            int r = u2 >> 5, cc = u2 & 31;
            float2 v = *(const float2*)&Wm[(size_t)(n0+r)*DD + kc*64 + cc*2];
            __nv_bfloat162 hb = __floats2bfloat162_rn(v.x, v.y);
            __nv_bfloat162 lb = __floats2bfloat162_rn(
                v.x - __bfloat162float(hb.x), v.y - __bfloat162float(hb.y));
            Wh[r*33 + cc] = *(const uint32_t*)&hb;
            Wl[r*33 + cc] = *(const uint32_t*)&lb;
        }
        __syncthreads();
        #pragma unroll
        for (int s = 0; s < 4; s++) {
            const int mb = wid*16;
            uint32_t ah[4], al[4];
            ah[0] = Xh[(mb+gr  )*33 + s*8 + kp];
            ah[1] = Xh[(mb+gr+8)*33 + s*8 + kp];
            ah[2] = Xh[(mb+gr  )*33 + s*8 + kp + 4];
            ah[3] = Xh[(mb+gr+8)*33 + s*8 + kp + 4];
            al[0] = Xl[(mb+gr  )*33 + s*8 + kp];
            al[1] = Xl[(mb+gr+8)*33 + s*8 + kp];
            al[2] = Xl[(mb+gr  )*33 + s*8 + kp + 4];
            al[3] = Xl[(mb+gr+8)*33 + s*8 + kp + 4];
            #pragma unroll
            for (int nt = 0; nt < 8; nt++) {
                uint32_t bh0 = Wh[(nt*8+gr)*33 + s*8 + kp];
                uint32_t bh1 = Wh[(nt*8+gr)*33 + s*8 + kp + 4];
                uint32_t bl0 = Wl[(nt*8+gr)*33 + s*8 + kp];
                uint32_t bl1 = Wl[(nt*8+gr)*33 + s*8 + kp + 4];
                mma_bf16(c[nt], ah, bh0, bh1);
                mma_bf16(c[nt], ah, bl0, bl1);
                mma_bf16(c[nt], al, bh0, bh1);
            }
        }
    }
    const float SCALE = 0.17677669529663687f;
    #pragma unroll
    for (int nt = 0; nt < 8; nt++) {
        #pragma unroll
        for (int hf = 0; hf < 2; hf++) {
            int m = m0 + wid*16 + gr + hf*8;
            int b = m >> 11, l = m & (LL-1);
            #pragma unroll
            for (int e = 0; e < 2; e++) {
                int n = n0 + nt*8 + kp*2 + e;
                float v = c[nt][hf*2 + e] + bm[n];
                int h = n >> 5, d = n & 31;
                size_t row = (size_t)(b*HH + h)*LL + l;
                if (blockIdx.z == 0) {
                    float sv = v * SCALE;
                    __nv_bfloat16 hi = __float2bfloat16(sv);
                    g_Q16[row*64 + d]      = hi;
                    g_Q16[row*64 + 32 + d] = __float2bfloat16(sv - __bfloat162float(hi));
                } else if (blockIdx.z == 1) {
                    __nv_bfloat16 hi = __float2bfloat16(v);
                    g_K16[row*64 + d]      = hi;
                    g_K16[row*64 + 32 + d] = __float2bfloat16(v - __bfloat162float(hi));
                } else {
                    g_V[row*HD + d] = v;
                }
            }
        }
    }
}

// ---------------- kernel 1b: V transpose + f16 hi/lo -------------------------
__global__ __launch_bounds__(256) void vt_kernel()
{
    __shared__ float Vsm[128][33];
    const int bh = blockIdx.x, l0 = blockIdx.y*128;
    const int tid = threadIdx.x;
    for (int idx = tid; idx < 128*32; idx += 256) {
        int i = idx >> 5, d = idx & 31;
        Vsm[i][d] = g_V[((size_t)bh*LL + l0 + i)*HD + d];
    }
    __syncthreads();
    for (int idx = tid; idx < 32*128; idx += 256) {
        int d = idx >> 7, i = idx & 127;
        float v = Vsm[i][d];
        __half hi = __float2half_rn(v);
        __half lo = __float2half_rn(v - __half2float(hi));
        g_VT16[((size_t)bh*64 + d)*LL + l0 + i]      = hi;
        g_VT16[((size_t)bh*64 + 32 + d)*LL + l0 + i] = lo;
    }
}

// ---------------- kernel 2: prior tables via prefix sum ----------------------
__global__ __launch_bounds__(256) void prior_kernel(const float* __restrict__ u)
{
    __shared__ float Es[LL];
    __shared__ float Ps[LL];
    __shared__ float part[256];
    const int h = blockIdx.x, tid = threadIdx.x;
    float uv = u[h];
    float cc = 0.5f / (uv*uv + 1e-6f);
    #pragma unroll
    for (int j = 0; j < 8; j++) {
        int d = tid + j*256;
        float fd = (float)d;
        float e = expf(-(fd*fd)*cc);
        Es[d] = e;
        g_E[h*LL + d] = e;
    }
    __syncthreads();
    float s = 0.f;
    #pragma unroll
    for (int i = 0; i < 8; i++) s += Es[tid*8 + i];
    part[tid] = s;
    __syncthreads();
    if (tid == 0) {
        float run = 0.f;
        for (int i = 0; i < 256; i++) { run += part[i]; part[i] = run; }
    }
    __syncthreads();
    float run = (tid == 0) ? 0.f : part[tid-1];
    #pragma unroll
    for (int i = 0; i < 8; i++) {
        run += Es[tid*8 + i];
        Ps[tid*8 + i] = run;
    }
    __syncthreads();
    float e0 = Es[0];
    #pragma unroll
    for (int j = 0; j < 8; j++) {
        int q = tid + j*256;
        g_rs[h*LL + q] = Ps[q] + Ps[LL-1-q] - e0;
    }
}

// ---------------- kernel 3: FUSED scores+softmax+disc+AV via mma.sync --------
#define SMF_R2   32960
#define SMF_ES   49600
#define SMF_QST  51648
#define SMF_IRS  52176
#define SMF_TOT  52192
#define SMF_BYTES (SMF_TOT*4)

__global__ __launch_bounds__(512,1) void attn_fused_kernel()
{
    extern __shared__ float sm[];
    float*    Srow = sm;
    uint32_t* PU   = (uint32_t*)sm;
    uint32_t* R2   = (uint32_t*)(sm + SMF_R2);
    float*    Es   = sm + SMF_ES;
    float*    Op   = sm + SMF_ES;
    uint32_t* Qst  = (uint32_t*)(sm + SMF_QST);
    float*    irs  = sm + SMF_IRS;

    const int tid = threadIdx.x, wid = tid >> 5, lane = tid & 31;
    const int gr = lane >> 2, kp = lane & 3;
    const int qt = blockIdx.x, bh = blockIdx.y;
    const int b = bh >> 3, h = bh & 7, q0 = qt * QT;

    {
        int r = tid >> 5, c = tid & 31;
        Qst[r*33 + c] = ((const uint32_t*)g_Q16)[((size_t)bh*LL + q0 + r)*32 + c];
    }
    for (int i = tid; i < LL; i += 512) Es[i] = g_E[h*LL + i];
    if (tid < QT) irs[tid] = 1.0f / (g_rs[h*LL + q0 + tid] + 1e-6f);
    __syncthreads();

    uint32_t qa[2][2][4];
    #pragma unroll
    for (int p = 0; p < 2; p++){
        int base = p*16;
        #pragma unroll
        for (int s = 0; s < 2; s++){
            qa[p][s][0] = Qst[ gr    *33 + base + kp     + 8*s];
            qa[p][s][1] = Qst[(gr+8) *33 + base + kp     + 8*s];
            qa[p][s][2] = Qst[ gr    *33 + base + kp + 4 + 8*s];
            qa[p][s][3] = Qst[(gr+8) *33 + base + kp + 4 + 8*s];
        }
    }

    // ---- phase 1: scores, 8 chunks of 256 keys, register-prefetched ---------
    {
        const uint4* Gk4 = (const uint4*)g_K16;
        const int key = (tid) >> 2, q4 = tid & 3;        // j=0 slot
        const int key1 = (tid + 512) >> 2, q41 = (tid + 512) & 3; // j=1 slot
        uint4 pk[4];
        {
            size_t r0 = (size_t)bh*LL + key;
            size_t r1 = (size_t)bh*LL + key1;
            pk[0] = Gk4[r0*8 + q4];  pk[1] = Gk4[r0*8 + 4 + q4];
            pk[2] = Gk4[r1*8 + q41]; pk[3] = Gk4[r1*8 + 4 + q41];
        }
        for (int kc = 0; kc < 8; kc++) {
            __syncthreads();
            *(uint4*)(R2 + key *20 + q4 *4)        = pk[0];
            *(uint4*)(R2 + 5120 + key *20 + q4 *4) = pk[1];
            *(uint4*)(R2 + key1*20 + q41*4)        = pk[2];
            *(uint4*)(R2 + 5120 + key1*20 + q41*4) = pk[3];
            __syncthreads();
            if (kc < 7) {
                size_t r0 = (size_t)bh*LL + (kc+1)*256 + key;
                size_t r1 = (size_t)bh*LL + (kc+1)*256 + key1;
                pk[0] = Gk4[r0*8 + q4];  pk[1] = Gk4[r0*8 + 4 + q4];
                pk[2] = Gk4[r1*8 + q41]; pk[3] = Gk4[r1*8 + 4 + q41];
            }
            #pragma unroll
            for (int t = 0; t < 2; t++) {
                int nt = wid*2 + t;
                int n0 = nt*8;
                float c[4] = {0.f,0.f,0.f,0.f};
                #pragma unroll
                for (int s = 0; s < 2; s++) {
                    uint32_t bh0 = R2[(n0+gr)*20 + kp     + 8*s];
                    uint32_t bh1 = R2[(n0+gr)*20 + kp + 4 + 8*s];
                    uint32_t bl0 = R2[5120 + (n0+gr)*20 + kp     + 8*s];
                    uint32_t bl1 = R2[5120 + (n0+gr)*20 + kp + 4 + 8*s];
                    mma_bf16(c, qa[0][s], bh0, bh1);
                    mma_bf16(c, qa[0][s], bl0, bl1);
                    mma_bf16(c, qa[1][s], bh0, bh1);
                }
                int col = kc*256 + n0 + kp*2;
                *(float2*)&Srow[ gr   *SPITCH + col] = make_float2(c[0], c[1]);
                *(float2*)&Srow[(gr+8)*SPITCH + col] = make_float2(c[2], c[3]);
            }
        }
    }
    __syncthreads();

    // ---- phase 2: softmax (float4 passes), in-place normalized f16 ----------
    {
        float* R = Srow + wid*SPITCH;
        const float4* R4 = (const float4*)R;
        float4* W4 = (float4*)R;
        float m = -3.4e38f;
        #pragma unroll
        for (int i = 0; i < 16; i++) {
            float4 v = R4[i*32 + lane];
            m = fmaxf(m, fmaxf(fmaxf(v.x, v.y), fmaxf(v.z, v.w)));
        }
        m = warpMax(m);
        float s = 0.f;
        #pragma unroll
        for (int i = 0; i < 16; i++) {
            float4 v = R4[i*32 + lane];
            v.x = __expf(v.x - m); v.y = __expf(v.y - m);
            v.z = __expf(v.z - m); v.w = __expf(v.w - m);
            s += v.x + v.y + v.z + v.w;
            W4[i*32 + lane] = v;
        }
        s = warpSum(s);
        float iv = 1.0f / s;
        uint2* W2 = (uint2*)R;
        #pragma unroll
        for (int i = 0; i < 16; i++) {
            float4 v = R4[i*32 + lane];
            __syncwarp();
            __half2 p0 = __floats2half2_rn(v.x*iv, v.y*iv);
            __half2 p1 = __floats2half2_rn(v.z*iv, v.w*iv);
            uint2 o;
            o.x = *(const uint32_t*)&p0;
            o.y = *(const uint32_t*)&p1;
            W2[i*32 + lane] = o;
        }
    }
    __syncthreads();

    // prefetch V chunk 0 (overlaps with phase 3)
    const uint4* Gv4 = (const uint4*)g_VT16;
    uint4 pv[8];
    #pragma unroll
    for (int j = 0; j < 4; j++) {
        int u2 = tid + j*512;
        int d = u2 >> 6, p4 = u2 & 63;
        pv[j*2]   = Gv4[((size_t)bh*64 + d)*256      + p4];
        pv[j*2+1] = Gv4[((size_t)bh*64 + 32 + d)*256 + p4];
    }

    // ---- phase 3: discrepancy partials (half2 reads, float2 stores) ---------
    {
        size_t pbase = (((size_t)(b*HH + h))*128 + qt) * LL;
        #pragma unroll
        for (int t = 0; t < 2; t++) {
            int k2 = tid + t*512;
            int k  = k2*2;
            float2 acc = make_float2(0.f, 0.f);
            #pragma unroll
            for (int q = 0; q < QT; q++) {
                uint32_t pa = PU[q*SPITCH + k2];
                __half2 h2 = *(const __half2*)&pa;
                float2 af = __half22float2(h2);
                float pr0 = Es[abs(q0 + q - k)]     * irs[q];
                float pr1 = Es[abs(q0 + q - k - 1)] * irs[q];
                acc.x += fabsf(af.x - pr0);
                acc.y += fabsf(af.y - pr1);
            }
            *(float2*)&g_dpart[pbase + k] = acc;
        }
    }

    // ---- phase 4: O = P @ V via mma.f16, register-prefetched ----------------
    {
        const int nt = wid & 3, seg = wid >> 2;
        uint32_t* Vhi = R2;
        uint32_t* Vlo = R2 + 8320;
        float c[4] = {0.f,0.f,0.f,0.f};

        for (int ch = 0; ch < 4; ch++) {
            __syncthreads();
            #pragma unroll
            for (int j = 0; j < 4; j++) {
                int u2 = tid + j*512;
                int d = u2 >> 6, p4 = u2 & 63;
                *(uint4*)(Vhi + d*260 + p4*4) = pv[j*2];
                *(uint4*)(Vlo + d*260 + p4*4) = pv[j*2+1];
            }
            __syncthreads();
            if (ch < 3) {
                #pragma unroll
                for (int j = 0; j < 4; j++) {
                    int u2 = tid + j*512;
                    int d = u2 >> 6, p4 = u2 & 63;
                    pv[j*2]   = Gv4[((size_t)bh*64 + d)*256      + (ch+1)*64 + p4];
                    pv[j*2+1] = Gv4[((size_t)bh*64 + 32 + d)*256 + (ch+1)*64 + p4];
                }
            }
            #pragma unroll
            for (int ks = 0; ks < 8; ks++) {
                int kg2 = ch*256 + seg*64 + ks*8;
                uint32_t a[4];
                a[0] = PU[ gr   *SPITCH + kg2 + kp];
                a[1] = PU[(gr+8)*SPITCH + kg2 + kp];
                a[2] = PU[ gr   *SPITCH + kg2 + kp + 4];
                a[3] = PU[(gr+8)*SPITCH + kg2 + kp + 4];
                int kb = seg*64 + ks*8;
                uint32_t bh0 = Vhi[(nt*8+gr)*260 + kb + kp];
                uint32_t bh1 = Vhi[(nt*8+gr)*260 + kb + kp + 4];
                uint32_t bl0 = Vlo[(nt*8+gr)*260 + kb + kp];
                uint32_t bl1 = Vlo[(nt*8+gr)*260 + kb + kp + 4];
                mma_f16(c, a, bh0, bh1);
                mma_f16(c, a, bl0, bl1);
            }
        }
        __syncthreads();
        int dcol = nt*8 + kp*2;
        Op[seg*512 +  gr   *32 + dcol]     = c[0];
        Op[seg*512 +  gr   *32 + dcol + 1] = c[1];
        Op[seg*512 + (gr+8)*32 + dcol]     = c[2];
        Op[seg*512 + (gr+8)*32 + dcol + 1] = c[3];
    }
    __syncthreads();
    {
        int q = tid >> 5, d = tid & 31;
        float s = Op[q*32 + d] + Op[512 + q*32 + d]
                + Op[1024 + q*32 + d] + Op[1536 + q*32 + d];
        g_O[((size_t)bh*LL + q0 + q)*HD + d] = s;
    }
}

// ---------------- kernel 4: discrepancy reduce (2-stage) ----------------------
__global__ void disc_reduce1_kernel()
{
    int k = blockIdx.x*256 + threadIdx.x;
    int seg = blockIdx.y;
    int b = k >> 11, kk = k & (LL-1);
    const float* base = g_dpart + (size_t)b*HH*128*LL + kk;
    float s = 0.f;
    #pragma unroll 8
    for (int p = seg*64; p < seg*64 + 64; p++) s += base[(size_t)p*LL];
    g_dpart2[seg*BB*LL + k] = s;
}
__global__ void disc_reduce2_kernel(float* __restrict__ dout)
{
    int idx = blockIdx.x*256 + threadIdx.x;
    float s = 0.f;
    #pragma unroll
    for (int seg = 0; seg < 16; seg++) s += g_dpart2[seg*BB*LL + idx];
    dout[idx] = s * (1.0f/(HH*(float)LL));
}

// ---------------- kernel 5: out projection via mma ---------------------------
__global__ __launch_bounds__(256) void outproj_mma_kernel(
    const float* __restrict__ Wo, const float* __restrict__ bo,
    float* __restrict__ out)
{
    extern __shared__ uint32_t usm[];
    uint32_t* Xh = usm;
    uint32_t* Xl = usm + LK_XL;
    uint32_t* Wh = usm + LK_WH;
    uint32_t* Wl = usm + LK_WL;

    const int m0 = blockIdx.y*128, n0 = blockIdx.x*64;
    const int tid = threadIdx.x, wid = tid>>5, lane = tid&31;
    const int gr = lane>>2, kp = lane&3;

    float c[8][4] = {};
    for (int kc = 0; kc < 4; kc++) {
        __syncthreads();
        #pragma unroll
        for (int j = 0; j < 16; j++) {
            int u2 = tid + j*256;
            int r = u2 >> 5, cc = u2 & 31;
            int m = m0 + r;
            int b = m >> 11, l = m & (LL-1);
            int k = kc*64 + cc*2;
            int hh = k >> 5, d = k & 31;
            float2 v = *(const float2*)&g_O[(((size_t)(b*HH + hh))*LL + l)*HD + d];
            __nv_bfloat162 hb = __floats2bfloat162_rn(v.x, v.y);
            __nv_bfloat162 lb = __floats2bfloat162_rn(
                v.x - __bfloat162float(hb.x), v.y - __bfloat162float(hb.y));
            Xh[r*33 + cc] = *(const uint32_t*)&hb;
            Xl[r*33 + cc] = *(const uint32_t*)&lb;
        }
        #pragma unroll
        for (int j = 0; j < 8; j++) {
            int u2 = tid + j*256;
            int r = u2 >> 5, cc = u2 & 31;
            float2 v = *(const float2*)&Wo[(size_t)(n0+r)*DD + kc*64 + cc*2];
            __nv_bfloat162 hb = __floats2bfloat162_rn(v.x, v.y);
            __nv_bfloat162 lb = __floats2bfloat162_rn(
                v.x - __bfloat162float(hb.x), v.y - __bfloat162float(hb.y));
            Wh[r*33 + cc] = *(const uint32_t*)&hb;
            Wl[r*33 + cc] = *(const uint32_t*)&lb;
        }
        __syncthreads();
        #pragma unroll
        for (int s = 0; s < 4; s++) {
            const int mb = wid*16;
            uint32_t ah[4], al[4];
            ah[0] = Xh[(mb+gr  )*33 + s*8 + kp];
            ah[1] = Xh[(mb+gr+8)*33 + s*8 + kp];
            ah[2] = Xh[(mb+gr  )*33 + s*8 + kp + 4];
            ah[3] = Xh[(mb+gr+8)*33 + s*8 + kp + 4];
            al[0] = Xl[(mb+gr  )*33 + s*8 + kp];
            al[1] = Xl[(mb+gr+8)*33 + s*8 + kp];
            al[2] = Xl[(mb+gr  )*33 + s*8 + kp + 4];
            al[3] = Xl[(mb+gr+8)*33 + s*8 + kp + 4];
            #pragma unroll
            for (int nt = 0; nt < 8; nt++) {
                uint32_t bh0 = Wh[(nt*8+gr)*33 + s*8 + kp];
                uint32_t bh1 = Wh[(nt*8+gr)*33 + s*8 + kp + 4];
                uint32_t bl0 = Wl[(nt*8+gr)*33 + s*8 + kp];
                uint32_t bl1 = Wl[(nt*8+gr)*33 + s*8 + kp + 4];
                mma_bf16(c[nt], ah, bh0, bh1);
                mma_bf16(c[nt], ah, bl0, bl1);
                mma_bf16(c[nt], al, bh0, bh1);
            }
        }
    }
    #pragma unroll
    for (int nt = 0; nt < 8; nt++) {
        #pragma unroll
        for (int hf = 0; hf < 2; hf++) {
            int m = m0 + wid*16 + gr + hf*8;
            int n = n0 + nt*8 + kp*2;
            float2 o;
            o.x = c[nt][hf*2]     + bo[n];
            o.y = c[nt][hf*2 + 1] + bo[n+1];
            *(float2*)&out[(size_t)m*DD + n] = o;
        }
    }
}

// ---------------- launch --------------------------------------------------------
extern "C" void kernel_launch(void* const* d_in, const int* in_sizes, int n_in,
                              void* d_out, int out_size)
{
    const float* x  = (const float*)d_in[0];
    const float* Wq = (const float*)d_in[1];
    const float* bq = (const float*)d_in[2];
    const float* Wk = (const float*)d_in[3];
    const float* bk = (const float*)d_in[4];
    const float* Wv = (const float*)d_in[5];
    const float* bv = (const float*)d_in[6];
    const float* u  = (const float*)d_in[7];
    const float* Wo = (const float*)d_in[8];
    const float* bo = (const float*)d_in[9];
    float* out = (float*)d_out;

    cudaFuncSetAttribute(attn_fused_kernel,
                         cudaFuncAttributeMaxDynamicSharedMemorySize, SMF_BYTES);
    cudaFuncSetAttribute(qkv_mma_kernel,
                         cudaFuncAttributeMaxDynamicSharedMemorySize, LK_TOT*4);
    cudaFuncSetAttribute(outproj_mma_kernel,
                         cudaFuncAttributeMaxDynamicSharedMemorySize, LK_TOT*4);

    qkv_mma_kernel<<<dim3(DD/64, (BB*LL)/128, 3), 256, LK_TOT*4>>>(
        x, Wq, bq, Wk, bk, Wv, bv);
    vt_kernel<<<dim3(BH, LL/128), 256>>>();
    prior_kernel<<<HH, 256>>>(u);
    attn_fused_kernel<<<dim3(LL/QT, BH), 512, SMF_BYTES>>>();
    disc_reduce1_kernel<<<dim3((BB*LL)/256, 16), 256>>>();
    disc_reduce2_kernel<<<(BB*LL)/256, 256>>>(out + (size_t)BB*LL*DD);
    outproj_mma_kernel<<<dim3(DD/64, (BB*LL)/128), 256, LK_TOT*4>>>(Wo, bo, out);
}